// round 4
// baseline (speedup 1.0000x reference)
#include <cuda_runtime.h>
#include <cstdint>
#include <cstddef>

// ---------------- problem dimensions ----------------
static constexpr int N_NODES = 16384;
static constexpr int NE      = 131072;
static constexpr int NE_RO   = 32768;
static constexpr int D       = 1024;
static constexpr int DL      = 300;
static constexpr int DS      = 16;
static constexpr int NC      = 117;

// ---------------- scratch layout ----------------
static constexpr size_t SZ_ND   = (size_t)N_NODES * D;
static constexpr size_t SZ_NDL  = (size_t)N_NODES * DL;
static constexpr size_t SZ_NC   = (size_t)N_NODES * NC;

static constexpr size_t OFF_P1   = 0;
static constexpr size_t OFF_P2   = OFF_P1  + SZ_ND;
static constexpr size_t OFF_NF   = OFF_P2  + SZ_ND;
static constexpr size_t OFF_Q1   = OFF_NF  + SZ_ND;
static constexpr size_t OFF_Q2   = OFF_Q1  + SZ_NDL;
static constexpr size_t OFF_NFL  = OFF_Q2  + SZ_NDL;
static constexpr size_t OFF_RD   = OFF_NFL + SZ_NDL;
static constexpr size_t OFF_RS   = OFF_RD  + SZ_NC;
static constexpr size_t OFF_AGG  = OFF_RS  + SZ_NC;
static constexpr size_t OFF_AGGL = OFF_AGG + SZ_ND;
static constexpr size_t TOTAL_SCRATCH = OFF_AGGL + SZ_NDL;

__device__ float g_scratch[TOTAL_SCRATCH];

// int scratch: deg[16384], row_start[16385], cursor[16384], perm[131072]
static constexpr size_t IOFF_DEG  = 0;
static constexpr size_t IOFF_RS_  = IOFF_DEG + N_NODES;
static constexpr size_t IOFF_CUR  = IOFF_RS_ + N_NODES + 1;
static constexpr size_t IOFF_PERM = IOFF_CUR + N_NODES;
__device__ int g_iscratch[IOFF_PERM + NE];

// ---------------- CSR build kernels ----------------
__global__ void zero_int_kernel(int* __restrict__ p, int n) {
    int i = blockIdx.x * blockDim.x + threadIdx.x;
    if (i < n) p[i] = 0;
}

__global__ void hist_kernel(const int* __restrict__ edst, int* __restrict__ deg) {
    int e = blockIdx.x * blockDim.x + threadIdx.x;
    if (e < NE) atomicAdd(&deg[edst[e]], 1);
}

// exclusive prefix over 16384 ints, one block of 512 threads x 32 elems
__global__ __launch_bounds__(512)
void scan_kernel(const int* __restrict__ deg, int* __restrict__ row_start,
                 int* __restrict__ cursor) {
    __shared__ int part[512];
    int tid = threadIdx.x;
    int base = tid * 32;
    int loc[32];
    int s = 0;
#pragma unroll
    for (int j = 0; j < 32; j++) { loc[j] = s; s += deg[base + j]; }
    part[tid] = s;
    __syncthreads();
    for (int off = 1; off < 512; off <<= 1) {
        int v = (tid >= off) ? part[tid - off] : 0;
        __syncthreads();
        part[tid] += v;
        __syncthreads();
    }
    int pre = (tid > 0) ? part[tid - 1] : 0;
#pragma unroll
    for (int j = 0; j < 32; j++) {
        int v = pre + loc[j];
        row_start[base + j] = v;
        cursor[base + j] = v;
    }
    if (tid == 511) row_start[N_NODES] = part[511];
}

__global__ void scatter_kernel(const int* __restrict__ edst, int* __restrict__ cursor,
                               int* __restrict__ perm) {
    int e = blockIdx.x * blockDim.x + threadIdx.x;
    if (e < NE) {
        int pos = atomicAdd(&cursor[edst[e]], 1);
        perm[pos] = e;
    }
}

// ---------------- bf16 split + mma helpers ----------------
__device__ __forceinline__ void bf16_split(float f0, float f1, uint32_t& hi, uint32_t& lo) {
    uint32_t h;
    asm("cvt.rn.satfinite.bf16x2.f32 %0, %1, %2;" : "=r"(h) : "f"(f1), "f"(f0));
    float h0 = __uint_as_float(h << 16);
    float h1 = __uint_as_float(h & 0xFFFF0000u);
    float r0 = f0 - h0;
    float r1 = f1 - h1;
    uint32_t l;
    asm("cvt.rn.satfinite.bf16x2.f32 %0, %1, %2;" : "=r"(l) : "f"(r1), "f"(r0));
    hi = h; lo = l;
}

__device__ __forceinline__ void mma_bf16(float* c, const uint32_t* a, const uint32_t* b) {
    asm volatile("mma.sync.aligned.m16n8k16.row.col.f32.bf16.bf16.f32 "
        "{%0,%1,%2,%3}, {%4,%5,%6,%7}, {%8,%9}, {%0,%1,%2,%3};"
        : "+f"(c[0]), "+f"(c[1]), "+f"(c[2]), "+f"(c[3])
        : "r"(a[0]), "r"(a[1]), "r"(a[2]), "r"(a[3]), "r"(b[0]), "r"(b[1]));
}

// ---------------- bf16x3 tensor-core GEMM ----------------
// C = act([A1|A2] @ B + bias). B given as two row-segment pointers:
//   row kg -> (kg < K1) ? B1[kg] : B2[kg-K1]   (row stride ldb)
// grid.z selects param set a/b (sibling GEMMs sharing A).
// SMEM: pre-split bf16 hi/lo tiles, uint32 [128][17] each (pad 17), double buffered.
static constexpr int TPAD    = 17;
static constexpr int ARR_U32 = 128 * TPAD;          // 2176
static constexpr int BUF_U32 = 4 * ARR_U32;         // Ahi, Alo, Bhi, Blo
static constexpr int GM_SMEM = 2 * BUF_U32 * 4;     // 69632 bytes

__global__ __launch_bounds__(256)
void gemm_mma(const float* __restrict__ A1, int K1,
              const float* __restrict__ A2, int K2,
              const float* __restrict__ B1a, const float* __restrict__ B2a, float* __restrict__ Ca,
              const float* __restrict__ B1b, const float* __restrict__ B2b, float* __restrict__ Cb,
              int ldb, const float* __restrict__ bias,
              int Nn, int doRelu)
{
    extern __shared__ uint32_t smu[];
    const float* B1 = (blockIdx.z == 0) ? B1a : B1b;
    const float* B2 = (blockIdx.z == 0) ? B2a : B2b;
    float*       Cm = (blockIdx.z == 0) ? Ca  : Cb;

    const int tid  = threadIdx.x;
    const int wid  = tid >> 5;
    const int lane = tid & 31;
    const int g    = lane >> 2;
    const int t    = lane & 3;
    const int m0   = blockIdx.y * 128;
    const int n0   = blockIdx.x * 128;
    const int K    = K1 + K2;
    const int nT   = (K + 31) / 32;
    const int wm   = wid & 3;
    const int wn   = wid >> 2;

    float acc[2][8][4];
#pragma unroll
    for (int i = 0; i < 2; i++)
#pragma unroll
        for (int j = 0; j < 8; j++)
#pragma unroll
            for (int k = 0; k < 4; k++) acc[i][j][k] = 0.f;

    float4 sa[4];
    float  sbf0[8], sbf1[8];

    // ---- stage tile tt into registers ----
    auto load_tile = [&](int tt) {
        const int k0 = tt * 32;
#pragma unroll
        for (int i = 0; i < 4; i++) {
            int idx = i * 256 + tid;
            int row = idx >> 3, c4 = idx & 7;
            int kb = k0 + c4 * 4;
            int m  = m0 + row;
            float4 v = make_float4(0.f, 0.f, 0.f, 0.f);
            if (kb < K1)      v = *(const float4*)(A1 + (size_t)m * K1 + kb);
            else if (kb < K)  v = *(const float4*)(A2 + (size_t)m * K2 + (kb - K1));
            sa[i] = v;
        }
#pragma unroll
        for (int i = 0; i < 8; i++) {
            int idx = i * 256 + tid;
            int kp = idx >> 7, n = idx & 127;   // kp 0..15, n 0..127
            int kg = k0 + kp * 2;               // even; K even => kg+1 in same segment
            int nn = n0 + n;
            float f0 = 0.f, f1 = 0.f;
            if (kg < K && nn < Nn) {
                const float* rp = (kg < K1) ? (B1 + (size_t)kg * ldb)
                                            : (B2 + (size_t)(kg - K1) * ldb);
                f0 = rp[nn];
                f1 = rp[ldb + nn];
            }
            sbf0[i] = f0; sbf1[i] = f1;
        }
    };

    // ---- split + commit to smem buffer ----
    auto store_tile = [&](int buf) {
        uint32_t* Ah = smu + buf * BUF_U32;
        uint32_t* Al = Ah + ARR_U32;
        uint32_t* Bh = Ah + 2 * ARR_U32;
        uint32_t* Bl = Ah + 3 * ARR_U32;
#pragma unroll
        for (int i = 0; i < 4; i++) {
            int idx = i * 256 + tid;
            int row = idx >> 3, c4 = idx & 7;
            uint32_t h0, l0, h1, l1;
            bf16_split(sa[i].x, sa[i].y, h0, l0);
            bf16_split(sa[i].z, sa[i].w, h1, l1);
            int o = row * TPAD + c4 * 2;
            Ah[o] = h0; Ah[o + 1] = h1;
            Al[o] = l0; Al[o + 1] = l1;
        }
#pragma unroll
        for (int i = 0; i < 8; i++) {
            int idx = i * 256 + tid;
            int kp = idx >> 7, n = idx & 127;
            uint32_t h, l;
            bf16_split(sbf0[i], sbf1[i], h, l);
            int o = n * TPAD + kp;
            Bh[o] = h; Bl[o] = l;
        }
    };

    // ---- compute on smem buffer ----
    auto compute = [&](int buf) {
        const uint32_t* Ah = smu + buf * BUF_U32 + (wm * 32) * TPAD;
        const uint32_t* Al = Ah + ARR_U32;
        const uint32_t* Bh = smu + buf * BUF_U32 + 2 * ARR_U32 + (wn * 64) * TPAD;
        const uint32_t* Bl = Bh + ARR_U32;
#pragma unroll
        for (int ks = 0; ks < 2; ks++) {
            uint32_t ah[2][4], al[2][4];
#pragma unroll
            for (int mb = 0; mb < 2; mb++) {
#pragma unroll
                for (int r = 0; r < 4; r++) {
                    int o = (mb * 16 + g + (r & 1) * 8) * TPAD + ks * 8 + t + (r >> 1) * 4;
                    ah[mb][r] = Ah[o];
                    al[mb][r] = Al[o];
                }
            }
#pragma unroll
            for (int nb = 0; nb < 8; nb++) {
                uint32_t bh[2], bl[2];
#pragma unroll
                for (int r = 0; r < 2; r++) {
                    int o = (nb * 8 + g) * TPAD + ks * 8 + t + r * 4;
                    bh[r] = Bh[o];
                    bl[r] = Bl[o];
                }
#pragma unroll
                for (int mb = 0; mb < 2; mb++) {
                    mma_bf16(acc[mb][nb], ah[mb], bh);
                    mma_bf16(acc[mb][nb], ah[mb], bl);
                    mma_bf16(acc[mb][nb], al[mb], bh);
                }
            }
        }
    };

    // ---- pipelined main loop ----
    load_tile(0);
    store_tile(0);
    __syncthreads();
    for (int tt = 0; tt < nT; tt++) {
        if (tt + 1 < nT) load_tile(tt + 1);
        compute(tt & 1);
        if (tt + 1 < nT) store_tile((tt + 1) & 1);
        __syncthreads();
    }

    // ---- epilogue ----
#pragma unroll
    for (int mb = 0; mb < 2; mb++) {
#pragma unroll
        for (int nb = 0; nb < 8; nb++) {
            int n = n0 + wn * 64 + nb * 8 + t * 2;
            float bv0 = 0.f, bv1 = 0.f;
            if (bias) {
                if (n     < Nn) bv0 = bias[n];
                if (n + 1 < Nn) bv1 = bias[n + 1];
            }
#pragma unroll
            for (int h = 0; h < 2; h++) {
                int m = m0 + wm * 32 + mb * 16 + g + h * 8;
                float v0 = acc[mb][nb][h * 2 + 0] + bv0;
                float v1 = acc[mb][nb][h * 2 + 1] + bv1;
                if (doRelu) { v0 = fmaxf(v0, 0.f); v1 = fmaxf(v1, 0.f); }
                float* cp = Cm + (size_t)m * Nn + n;
                if ((Nn & 1) == 0) {
                    if (n + 1 < Nn) *(float2*)cp = make_float2(v0, v1);
                    else if (n < Nn) cp[0] = v0;
                } else {
                    if (n     < Nn) cp[0] = v0;
                    if (n + 1 < Nn) cp[1] = v1;
                }
            }
        }
    }
}

// ---------------- appearance aggregation (gather, no atomics) ----------------
// agg[n] = (1/max(deg,1)) * sum_{e in-edges(n)} relu(P1[src_e] + P2[n] + s_f[e]@Ws + b_e)
__global__ __launch_bounds__(256)
void agg_app_kernel(const float* __restrict__ P1, const float* __restrict__ P2,
                    const float* __restrict__ b_e, const float* __restrict__ Ws,
                    const float* __restrict__ s_f,
                    const int* __restrict__ esrc, const int* __restrict__ perm,
                    const int* __restrict__ row_start,
                    float* __restrict__ agg)
{
    const int n = blockIdx.x;
    const int tid = threadIdx.x;
    const int start = row_start[n];
    const int nb = row_start[n + 1] - start;

    __shared__ float sf[2][DS];

    float4 base = ((const float4*)(P2 + (size_t)n * D))[tid];
    float4 be   = ((const float4*)b_e)[tid];
    base.x += be.x; base.y += be.y; base.z += be.z; base.w += be.w;

    // spatial weight columns for this thread, held in registers
    float4 w[DS];
    const float4* Ws4 = (const float4*)Ws;
#pragma unroll
    for (int k = 0; k < DS; k++) w[k] = Ws4[(size_t)k * 256 + tid];

    float4 acc = make_float4(0.f, 0.f, 0.f, 0.f);
    for (int i = 0; i < nb; i++) {
        int e = perm[start + i];
        if (tid < DS) sf[i & 1][tid] = s_f[(size_t)e * DS + tid];
        __syncthreads();
        int s = esrc[e];
        float4 v = ((const float4*)(P1 + (size_t)s * D))[tid];
        v.x += base.x; v.y += base.y; v.z += base.z; v.w += base.w;
#pragma unroll
        for (int k = 0; k < DS; k++) {
            float f = sf[i & 1][k];
            v.x += f * w[k].x; v.y += f * w[k].y; v.z += f * w[k].z; v.w += f * w[k].w;
        }
        acc.x += fmaxf(v.x, 0.f); acc.y += fmaxf(v.y, 0.f);
        acc.z += fmaxf(v.z, 0.f); acc.w += fmaxf(v.w, 0.f);
    }
    float inv = 1.0f / (float)max(nb, 1);
    acc.x *= inv; acc.y *= inv; acc.z *= inv; acc.w *= inv;
    ((float4*)(agg + (size_t)n * D))[tid] = acc;
}

// ---------------- language aggregation (gather, no atomics) ----------------
__global__ __launch_bounds__(128)
void agg_lang_kernel(const float* __restrict__ Q1, const float* __restrict__ Q2,
                     const float* __restrict__ b_el,
                     const int* __restrict__ esrc, const int* __restrict__ perm,
                     const int* __restrict__ row_start,
                     float* __restrict__ aggl)
{
    const int n = blockIdx.x;
    const int c4 = threadIdx.x;
    if (c4 >= DL / 4) return;
    const int start = row_start[n];
    const int nb = row_start[n + 1] - start;

    float4 base = ((const float4*)(Q2 + (size_t)n * DL))[c4];
    float4 be   = ((const float4*)b_el)[c4];
    base.x += be.x; base.y += be.y; base.z += be.z; base.w += be.w;

    float4 acc = make_float4(0.f, 0.f, 0.f, 0.f);
    for (int i = 0; i < nb; i++) {
        int e = perm[start + i];
        int s = esrc[e];
        float4 v = ((const float4*)(Q1 + (size_t)s * DL))[c4];
        acc.x += fmaxf(v.x + base.x, 0.f);
        acc.y += fmaxf(v.y + base.y, 0.f);
        acc.z += fmaxf(v.z + base.z, 0.f);
        acc.w += fmaxf(v.w + base.w, 0.f);
    }
    float inv = 1.0f / (float)max(nb, 1);
    acc.x *= inv; acc.y *= inv; acc.z *= inv; acc.w *= inv;
    ((float4*)(aggl + (size_t)n * DL))[c4] = acc;
}

// ---------------- readout ----------------
__global__ __launch_bounds__(128)
void readout_kernel(const float* __restrict__ Rd, const float* __restrict__ Rs,
                    const float* __restrict__ W_p, const float* __restrict__ b_p,
                    const float* __restrict__ s_f_ro,
                    const int* __restrict__ rsrc, const int* __restrict__ rdst,
                    float* __restrict__ pred)
{
    int e = blockIdx.x;
    __shared__ float sf[DS];
    if (threadIdx.x < DS) sf[threadIdx.x] = s_f_ro[(size_t)e * DS + threadIdx.x];
    __syncthreads();
    int c = threadIdx.x;
    if (c >= NC) return;
    int s = rsrc[e];
    int d = rdst[e];
    float acc = Rd[(size_t)d * NC + c] + Rs[(size_t)s * NC + c] + b_p[c];
    const float* Wp3 = W_p + (size_t)(D + DL) * NC;
#pragma unroll
    for (int k = 0; k < DS; k++)
        acc += sf[k] * Wp3[(size_t)k * NC + c];
    pred[(size_t)e * NC + c] = acc;
}

// ---------------- host launcher ----------------
extern "C" void kernel_launch(void* const* d_in, const int* in_sizes, int n_in,
                              void* d_out, int out_size)
{
    const float* feat   = (const float*)d_in[0];
    const float* w2v    = (const float*)d_in[1];
    const float* s_f    = (const float*)d_in[2];
    const float* s_f_ro = (const float*)d_in[3];
    const float* W_e    = (const float*)d_in[4];
    const float* b_e    = (const float*)d_in[5];
    const float* W_el   = (const float*)d_in[6];
    const float* b_el   = (const float*)d_in[7];
    const float* W_nu   = (const float*)d_in[8];
    const float* b_nu   = (const float*)d_in[9];
    const float* W_nul  = (const float*)d_in[10];
    const float* b_nul  = (const float*)d_in[11];
    const float* W_p    = (const float*)d_in[12];
    const float* b_p    = (const float*)d_in[13];
    const int* esrc = (const int*)d_in[14];
    const int* edst = (const int*)d_in[15];
    const int* rsrc = (const int*)d_in[16];
    const int* rdst = (const int*)d_in[17];
    float* pred = (float*)d_out;

    float* sc = nullptr;
    cudaGetSymbolAddress((void**)&sc, g_scratch);
    int* isc = nullptr;
    cudaGetSymbolAddress((void**)&isc, g_iscratch);

    float* P1   = sc + OFF_P1;
    float* P2   = sc + OFF_P2;
    float* NF   = sc + OFF_NF;
    float* Q1   = sc + OFF_Q1;
    float* Q2   = sc + OFF_Q2;
    float* NFL  = sc + OFF_NFL;
    float* RD   = sc + OFF_RD;
    float* RS   = sc + OFF_RS;
    float* AGG  = sc + OFF_AGG;
    float* AGGL = sc + OFF_AGGL;

    int* deg  = isc + IOFF_DEG;
    int* rows = isc + IOFF_RS_;
    int* cur  = isc + IOFF_CUR;
    int* perm = isc + IOFF_PERM;

    cudaFuncSetAttribute(gemm_mma, cudaFuncAttributeMaxDynamicSharedMemorySize, GM_SMEM);

    // ---- CSR build (by dst) ----
    zero_int_kernel<<<(N_NODES + 255) / 256, 256>>>(deg, N_NODES);
    hist_kernel<<<NE / 256, 256>>>(edst, deg);
    scan_kernel<<<1, 512>>>(deg, rows, cur);
    scatter_kernel<<<NE / 256, 256>>>(edst, cur, perm);

    dim3 blk(256);

    // ---- node-level pre-projections (sibling pairs merged via grid.z) ----
    gemm_mma<<<dim3(8, 128, 2), blk, GM_SMEM>>>(
        feat, D, nullptr, 0,
        W_e, W_e, P1,
        W_e + (size_t)D * D, W_e + (size_t)D * D, P2,
        D, nullptr, D, 0);
    gemm_mma<<<dim3(3, 128, 2), blk, GM_SMEM>>>(
        w2v, DL, nullptr, 0,
        W_el, W_el, Q1,
        W_el + (size_t)DL * DL, W_el + (size_t)DL * DL, Q2,
        DL, nullptr, DL, 0);

    // ---- edge aggregation (gather) ----
    agg_app_kernel<<<N_NODES, 256>>>(P1, P2, b_e, W_e + (size_t)(2 * D) * D,
                                     s_f, esrc, perm, rows, AGG);
    agg_lang_kernel<<<N_NODES, 128>>>(Q1, Q2, b_el, esrc, perm, rows, AGGL);

    // ---- node updates ----
    gemm_mma<<<dim3(8, 128, 1), blk, GM_SMEM>>>(
        feat, D, AGG, D,
        W_nu, W_nu + (size_t)D * D, NF,
        W_nu, W_nu + (size_t)D * D, NF,
        D, b_nu, D, 1);
    gemm_mma<<<dim3(3, 128, 1), blk, GM_SMEM>>>(
        w2v, DL, AGGL, DL,
        W_nul, W_nul + (size_t)DL * DL, NFL,
        W_nul, W_nul + (size_t)DL * DL, NFL,
        DL, b_nul, DL, 1);

    // ---- predictor pre-projections (RD & RS merged; RS uses split B rows) ----
    gemm_mma<<<dim3(1, 128, 2), blk, GM_SMEM>>>(
        NF, D, NFL, DL,
        W_p,                          W_p + (size_t)D * NC,          RD,
        W_p + (size_t)(D + DL + DS + DL) * NC, W_p + (size_t)(D + DL + DS) * NC, RS,
        NC, nullptr, NC, 0);

    // ---- final edge readout ----
    readout_kernel<<<NE_RO, 128>>>(RD, RS, W_p, b_p, s_f_ro, rsrc, rdst, pred);
}

// round 5
// speedup vs baseline: 1.1432x; 1.1432x over previous
#include <cuda_runtime.h>
#include <cstdint>
#include <cstddef>

// ---------------- problem dimensions ----------------
static constexpr int N_NODES = 16384;
static constexpr int NE      = 131072;
static constexpr int NE_RO   = 32768;
static constexpr int D       = 1024;
static constexpr int DL      = 300;
static constexpr int DS      = 16;
static constexpr int NC      = 117;

// ---------------- scratch layout ----------------
static constexpr size_t SZ_ND   = (size_t)N_NODES * D;
static constexpr size_t SZ_NDL  = (size_t)N_NODES * DL;
static constexpr size_t SZ_NC   = (size_t)N_NODES * NC;
static constexpr size_t SZ_SP   = (size_t)NE * D;        // 134.2M floats
static constexpr size_t SZ_SPRO = (size_t)NE_RO * NC;

static constexpr size_t OFF_P1   = 0;
static constexpr size_t OFF_P2   = OFF_P1  + SZ_ND;
static constexpr size_t OFF_NF   = OFF_P2  + SZ_ND;
static constexpr size_t OFF_Q1   = OFF_NF  + SZ_ND;
static constexpr size_t OFF_Q2   = OFF_Q1  + SZ_NDL;
static constexpr size_t OFF_NFL  = OFF_Q2  + SZ_NDL;
static constexpr size_t OFF_RD   = OFF_NFL + SZ_NDL;
static constexpr size_t OFF_RS   = OFF_RD  + SZ_NC;
static constexpr size_t OFF_AGG  = OFF_RS  + SZ_NC;
static constexpr size_t OFF_AGGL = OFF_AGG + SZ_ND;
static constexpr size_t OFF_SPRO = OFF_AGGL + SZ_NDL;
static constexpr size_t OFF_SP   = OFF_SPRO + SZ_SPRO;
static constexpr size_t TOTAL_SCRATCH = OFF_SP + SZ_SP;

__device__ float g_scratch[TOTAL_SCRATCH];

// int scratch: deg[16384], row_start[16385], cursor[16384], perm[131072]
static constexpr size_t IOFF_DEG  = 0;
static constexpr size_t IOFF_RS_  = IOFF_DEG + N_NODES;
static constexpr size_t IOFF_CUR  = IOFF_RS_ + N_NODES + 1;
static constexpr size_t IOFF_PERM = IOFF_CUR + N_NODES;
__device__ int g_iscratch[IOFF_PERM + NE];

// ---------------- CSR build kernels ----------------
__global__ void zero_int_kernel(int* __restrict__ p, int n) {
    int i = blockIdx.x * blockDim.x + threadIdx.x;
    if (i < n) p[i] = 0;
}

__global__ void hist_kernel(const int* __restrict__ edst, int* __restrict__ deg) {
    int e = blockIdx.x * blockDim.x + threadIdx.x;
    if (e < NE) atomicAdd(&deg[edst[e]], 1);
}

__global__ __launch_bounds__(512)
void scan_kernel(const int* __restrict__ deg, int* __restrict__ row_start,
                 int* __restrict__ cursor) {
    __shared__ int part[512];
    int tid = threadIdx.x;
    int base = tid * 32;
    int loc[32];
    int s = 0;
#pragma unroll
    for (int j = 0; j < 32; j++) { loc[j] = s; s += deg[base + j]; }
    part[tid] = s;
    __syncthreads();
    for (int off = 1; off < 512; off <<= 1) {
        int v = (tid >= off) ? part[tid - off] : 0;
        __syncthreads();
        part[tid] += v;
        __syncthreads();
    }
    int pre = (tid > 0) ? part[tid - 1] : 0;
#pragma unroll
    for (int j = 0; j < 32; j++) {
        int v = pre + loc[j];
        row_start[base + j] = v;
        cursor[base + j] = v;
    }
    if (tid == 511) row_start[N_NODES] = part[511];
}

__global__ void scatter_kernel(const int* __restrict__ edst, int* __restrict__ cursor,
                               int* __restrict__ perm) {
    int e = blockIdx.x * blockDim.x + threadIdx.x;
    if (e < NE) {
        int pos = atomicAdd(&cursor[edst[e]], 1);
        perm[pos] = e;
    }
}

// ---------------- bf16 split + mma helpers ----------------
__device__ __forceinline__ void bf16_split(float f0, float f1, uint32_t& hi, uint32_t& lo) {
    uint32_t h;
    asm("cvt.rn.satfinite.bf16x2.f32 %0, %1, %2;" : "=r"(h) : "f"(f1), "f"(f0));
    float h0 = __uint_as_float(h << 16);
    float h1 = __uint_as_float(h & 0xFFFF0000u);
    float r0 = f0 - h0;
    float r1 = f1 - h1;
    uint32_t l;
    asm("cvt.rn.satfinite.bf16x2.f32 %0, %1, %2;" : "=r"(l) : "f"(r1), "f"(r0));
    hi = h; lo = l;
}

__device__ __forceinline__ void mma_bf16(float* c, const uint32_t* a, const uint32_t* b) {
    asm volatile("mma.sync.aligned.m16n8k16.row.col.f32.bf16.bf16.f32 "
        "{%0,%1,%2,%3}, {%4,%5,%6,%7}, {%8,%9}, {%0,%1,%2,%3};"
        : "+f"(c[0]), "+f"(c[1]), "+f"(c[2]), "+f"(c[3])
        : "r"(a[0]), "r"(a[1]), "r"(a[2]), "r"(a[3]), "r"(b[0]), "r"(b[1]));
}

// ---------------- bf16x3 tensor-core GEMM (R3 body; z-select for merged launches) ----------------
// C = act([A1|A2] @ B + bias), B row-major [K1+K2, ldb].
// CTA tile 128x128, K-tile 32, 8 warps (warp tile 32x64), double-buffered SMEM.
static constexpr int A_PAD   = 40;
static constexpr int B_PAD   = 132;
static constexpr int A_FLTS  = 128 * A_PAD;
static constexpr int B_FLTS  = 32 * B_PAD;
static constexpr int BUF_FLTS = A_FLTS + B_FLTS;
static constexpr int GM_SMEM  = 2 * BUF_FLTS * 4;   // 74752 bytes

__global__ __launch_bounds__(256)
void gemm_mma(const float* __restrict__ A1a, int K1a, const float* __restrict__ A2a, int K2a,
              const float* __restrict__ Ba, float* __restrict__ Ca,
              const float* __restrict__ A1b, int K1b, const float* __restrict__ A2b, int K2b,
              const float* __restrict__ Bb, float* __restrict__ Cb,
              int ldb, const float* __restrict__ bias,
              int Nn, int doRelu)
{
    extern __shared__ float sm[];
    const float* A1; const float* A2; const float* B; float* Cmat; int K1, K2;
    if (blockIdx.z == 0) { A1 = A1a; K1 = K1a; A2 = A2a; K2 = K2a; B = Ba; Cmat = Ca; }
    else                 { A1 = A1b; K1 = K1b; A2 = A2b; K2 = K2b; B = Bb; Cmat = Cb; }

    const int tid  = threadIdx.x;
    const int wid  = tid >> 5;
    const int lane = tid & 31;
    const int g    = lane >> 2;
    const int t    = lane & 3;
    const int m0   = blockIdx.y * 128;
    const int n0   = blockIdx.x * 128;
    const int K    = K1 + K2;
    const int nT   = (K + 31) / 32;
    const int wm   = wid & 3;
    const int wn   = wid >> 2;
    const bool b_vec = ((ldb & 3) == 0);

    float acc[2][8][4];
#pragma unroll
    for (int i = 0; i < 2; i++)
#pragma unroll
        for (int j = 0; j < 8; j++)
#pragma unroll
            for (int k = 0; k < 4; k++) acc[i][j][k] = 0.f;

    float4 sa[4], sb[4];

    auto load_tile = [&](int tt) {
        const int k0 = tt * 32;
#pragma unroll
        for (int i = 0; i < 4; i++) {
            int idx = i * 256 + tid;
            int row = idx >> 3, c4 = idx & 7;
            int kb = k0 + c4 * 4;
            int m  = m0 + row;
            float4 v = make_float4(0.f, 0.f, 0.f, 0.f);
            if (kb < K1)      v = *(const float4*)(A1 + (size_t)m * K1 + kb);
            else if (kb < K)  v = *(const float4*)(A2 + (size_t)m * K2 + (kb - K1));
            sa[i] = v;
        }
#pragma unroll
        for (int i = 0; i < 4; i++) {
            int idx = i * 256 + tid;
            int k = idx >> 5, n4 = idx & 31;
            int kg = k0 + k;
            int nb4 = n0 + n4 * 4;
            float4 v = make_float4(0.f, 0.f, 0.f, 0.f);
            if (kg < K) {
                const float* br = B + (size_t)kg * ldb;
                if (b_vec && nb4 + 3 < Nn) {
                    v = *(const float4*)(br + nb4);
                } else {
                    if (nb4     < Nn) v.x = br[nb4];
                    if (nb4 + 1 < Nn) v.y = br[nb4 + 1];
                    if (nb4 + 2 < Nn) v.z = br[nb4 + 2];
                    if (nb4 + 3 < Nn) v.w = br[nb4 + 3];
                }
            }
            sb[i] = v;
        }
    };

    auto store_tile = [&](int buf) {
        float* As = sm + buf * BUF_FLTS;
        float* Bs = As + A_FLTS;
#pragma unroll
        for (int i = 0; i < 4; i++) {
            int idx = i * 256 + tid;
            int row = idx >> 3, c4 = idx & 7;
            *(float4*)(As + row * A_PAD + c4 * 4) = sa[i];
        }
#pragma unroll
        for (int i = 0; i < 4; i++) {
            int idx = i * 256 + tid;
            int k = idx >> 5, n4 = idx & 31;
            *(float4*)(Bs + k * B_PAD + n4 * 4) = sb[i];
        }
    };

    auto compute = [&](int buf) {
        const float* As = sm + buf * BUF_FLTS + (wm * 32) * A_PAD;
        const float* Bs = sm + buf * BUF_FLTS + A_FLTS + wn * 64;
#pragma unroll
        for (int ks = 0; ks < 2; ks++) {
            uint32_t ahi[2][4], alo[2][4];
#pragma unroll
            for (int mb = 0; mb < 2; mb++) {
#pragma unroll
                for (int r = 0; r < 4; r++) {
                    int rowq = mb * 16 + g + (r & 1) * 8;
                    int kq   = ks * 16 + t * 2 + (r >> 1) * 8;
                    float2 f = *(const float2*)(As + rowq * A_PAD + kq);
                    bf16_split(f.x, f.y, ahi[mb][r], alo[mb][r]);
                }
            }
            uint32_t bhi[8][2], blo[8][2];
#pragma unroll
            for (int nb = 0; nb < 8; nb++) {
#pragma unroll
                for (int r = 0; r < 2; r++) {
                    int kq = ks * 16 + t * 2 + r * 8;
                    float f0 = Bs[kq * B_PAD + nb * 8 + g];
                    float f1 = Bs[(kq + 1) * B_PAD + nb * 8 + g];
                    bf16_split(f0, f1, bhi[nb][r], blo[nb][r]);
                }
            }
#pragma unroll
            for (int mb = 0; mb < 2; mb++) {
#pragma unroll
                for (int nb = 0; nb < 8; nb++) {
                    mma_bf16(acc[mb][nb], ahi[mb], bhi[nb]);
                    mma_bf16(acc[mb][nb], ahi[mb], blo[nb]);
                    mma_bf16(acc[mb][nb], alo[mb], bhi[nb]);
                }
            }
        }
    };

    load_tile(0);
    store_tile(0);
    __syncthreads();
    for (int tt = 0; tt < nT; tt++) {
        if (tt + 1 < nT) load_tile(tt + 1);
        compute(tt & 1);
        if (tt + 1 < nT) store_tile((tt + 1) & 1);
        __syncthreads();
    }

#pragma unroll
    for (int mb = 0; mb < 2; mb++) {
#pragma unroll
        for (int nb = 0; nb < 8; nb++) {
            int n = n0 + wn * 64 + nb * 8 + t * 2;
            float bv0 = 0.f, bv1 = 0.f;
            if (bias) {
                if (n     < Nn) bv0 = bias[n];
                if (n + 1 < Nn) bv1 = bias[n + 1];
            }
#pragma unroll
            for (int h = 0; h < 2; h++) {
                int m = m0 + wm * 32 + mb * 16 + g + h * 8;
                float v0 = acc[mb][nb][h * 2 + 0] + bv0;
                float v1 = acc[mb][nb][h * 2 + 1] + bv1;
                if (doRelu) { v0 = fmaxf(v0, 0.f); v1 = fmaxf(v1, 0.f); }
                float* cp = Cmat + (size_t)m * Nn + n;
                if ((Nn & 1) == 0) {
                    if (n + 1 < Nn) *(float2*)cp = make_float2(v0, v1);
                    else if (n < Nn) cp[0] = v0;
                } else {
                    if (n     < Nn) cp[0] = v0;
                    if (n + 1 < Nn) cp[1] = v1;
                }
            }
        }
    }
}

// ---------------- appearance aggregation (CSR gather, no atomics, no syncs) ----------------
// agg[n] = mean over in-edges of relu(P1[src] + SP[e] + P2[n] + b_e)
__global__ __launch_bounds__(256)
void agg_app_kernel(const float* __restrict__ P1, const float* __restrict__ P2,
                    const float* __restrict__ SP, const float* __restrict__ b_e,
                    const int* __restrict__ esrc, const int* __restrict__ perm,
                    const int* __restrict__ row_start,
                    float* __restrict__ agg)
{
    const int n = blockIdx.x;
    const int tid = threadIdx.x;
    const int start = row_start[n];
    const int nb = row_start[n + 1] - start;

    float4 base = ((const float4*)(P2 + (size_t)n * D))[tid];
    float4 be   = ((const float4*)b_e)[tid];
    base.x += be.x; base.y += be.y; base.z += be.z; base.w += be.w;

    float4 acc = make_float4(0.f, 0.f, 0.f, 0.f);
#pragma unroll 2
    for (int i = 0; i < nb; i++) {
        int e = __ldg(&perm[start + i]);
        int s = __ldg(&esrc[e]);
        float4 v1 = ((const float4*)(P1 + (size_t)s * D))[tid];
        float4 v2 = ((const float4*)(SP + (size_t)e * D))[tid];
        acc.x += fmaxf(v1.x + v2.x + base.x, 0.f);
        acc.y += fmaxf(v1.y + v2.y + base.y, 0.f);
        acc.z += fmaxf(v1.z + v2.z + base.z, 0.f);
        acc.w += fmaxf(v1.w + v2.w + base.w, 0.f);
    }
    float inv = 1.0f / (float)max(nb, 1);
    acc.x *= inv; acc.y *= inv; acc.z *= inv; acc.w *= inv;
    ((float4*)(agg + (size_t)n * D))[tid] = acc;
}

// ---------------- language aggregation (CSR gather) ----------------
__global__ __launch_bounds__(96)
void agg_lang_kernel(const float* __restrict__ Q1, const float* __restrict__ Q2,
                     const float* __restrict__ b_el,
                     const int* __restrict__ esrc, const int* __restrict__ perm,
                     const int* __restrict__ row_start,
                     float* __restrict__ aggl)
{
    const int n = blockIdx.x;
    const int c4 = threadIdx.x;
    if (c4 >= DL / 4) return;
    const int start = row_start[n];
    const int nb = row_start[n + 1] - start;

    float4 base = ((const float4*)(Q2 + (size_t)n * DL))[c4];
    float4 be   = ((const float4*)b_el)[c4];
    base.x += be.x; base.y += be.y; base.z += be.z; base.w += be.w;

    float4 acc = make_float4(0.f, 0.f, 0.f, 0.f);
#pragma unroll 2
    for (int i = 0; i < nb; i++) {
        int e = __ldg(&perm[start + i]);
        int s = __ldg(&esrc[e]);
        float4 v = ((const float4*)(Q1 + (size_t)s * DL))[c4];
        acc.x += fmaxf(v.x + base.x, 0.f);
        acc.y += fmaxf(v.y + base.y, 0.f);
        acc.z += fmaxf(v.z + base.z, 0.f);
        acc.w += fmaxf(v.w + base.w, 0.f);
    }
    float inv = 1.0f / (float)max(nb, 1);
    acc.x *= inv; acc.y *= inv; acc.z *= inv; acc.w *= inv;
    ((float4*)(aggl + (size_t)n * DL))[c4] = acc;
}

// ---------------- readout: pred = Rd[dst] + Rs[src] + SPro[e] ----------------
__global__ __launch_bounds__(128)
void readout_kernel(const float* __restrict__ Rd, const float* __restrict__ Rs,
                    const float* __restrict__ SPro,
                    const int* __restrict__ rsrc, const int* __restrict__ rdst,
                    float* __restrict__ pred)
{
    int e = blockIdx.x;
    int c = threadIdx.x;
    if (c >= NC) return;
    int s = rsrc[e];
    int d = rdst[e];
    pred[(size_t)e * NC + c] = Rd[(size_t)d * NC + c] + Rs[(size_t)s * NC + c]
                             + SPro[(size_t)e * NC + c];
}

// ---------------- host launcher ----------------
extern "C" void kernel_launch(void* const* d_in, const int* in_sizes, int n_in,
                              void* d_out, int out_size)
{
    const float* feat   = (const float*)d_in[0];
    const float* w2v    = (const float*)d_in[1];
    const float* s_f    = (const float*)d_in[2];
    const float* s_f_ro = (const float*)d_in[3];
    const float* W_e    = (const float*)d_in[4];
    const float* b_e    = (const float*)d_in[5];
    const float* W_el   = (const float*)d_in[6];
    const float* b_el   = (const float*)d_in[7];
    const float* W_nu   = (const float*)d_in[8];
    const float* b_nu   = (const float*)d_in[9];
    const float* W_nul  = (const float*)d_in[10];
    const float* b_nul  = (const float*)d_in[11];
    const float* W_p    = (const float*)d_in[12];
    const float* b_p    = (const float*)d_in[13];
    const int* esrc = (const int*)d_in[14];
    const int* edst = (const int*)d_in[15];
    const int* rsrc = (const int*)d_in[16];
    const int* rdst = (const int*)d_in[17];
    float* pred = (float*)d_out;

    float* sc = nullptr;
    cudaGetSymbolAddress((void**)&sc, g_scratch);
    int* isc = nullptr;
    cudaGetSymbolAddress((void**)&isc, g_iscratch);

    float* P1   = sc + OFF_P1;
    float* P2   = sc + OFF_P2;
    float* NF   = sc + OFF_NF;
    float* Q1   = sc + OFF_Q1;
    float* Q2   = sc + OFF_Q2;
    float* NFL  = sc + OFF_NFL;
    float* RD   = sc + OFF_RD;
    float* RS   = sc + OFF_RS;
    float* AGG  = sc + OFF_AGG;
    float* AGGL = sc + OFF_AGGL;
    float* SPRO = sc + OFF_SPRO;
    float* SP   = sc + OFF_SP;

    int* deg  = isc + IOFF_DEG;
    int* rows = isc + IOFF_RS_;
    int* cur  = isc + IOFF_CUR;
    int* perm = isc + IOFF_PERM;

    cudaFuncSetAttribute(gemm_mma, cudaFuncAttributeMaxDynamicSharedMemorySize, GM_SMEM);

    // ---- CSR build (by dst) ----
    zero_int_kernel<<<(N_NODES + 255) / 256, 256>>>(deg, N_NODES);
    hist_kernel<<<NE / 256, 256>>>(edst, deg);
    scan_kernel<<<1, 512>>>(deg, rows, cur);
    scatter_kernel<<<NE / 256, 256>>>(edst, cur, perm);

    dim3 blk(256);
    const float* Ws   = W_e + (size_t)(2 * D) * D;          // spatial rows of W_e
    const float* Wp3  = W_p + (size_t)(D + DL) * NC;        // spatial rows of W_p

    // ---- spatial pre-projections (hoists Ws out of the edge loop) ----
    // SP[e] = s_f @ Ws              [131072, 1024]
    gemm_mma<<<dim3(8, 1024, 1), blk, GM_SMEM>>>(
        s_f, DS, nullptr, 0, Ws, SP,
        s_f, DS, nullptr, 0, Ws, SP,
        D, nullptr, D, 0);
    // SPro[e] = s_f_ro @ Wp3 + b_p  [32768, 117]
    gemm_mma<<<dim3(1, 256, 1), blk, GM_SMEM>>>(
        s_f_ro, DS, nullptr, 0, Wp3, SPRO,
        s_f_ro, DS, nullptr, 0, Wp3, SPRO,
        NC, b_p, NC, 0);

    // ---- node-level pre-projections (siblings merged via grid.z) ----
    gemm_mma<<<dim3(8, 128, 2), blk, GM_SMEM>>>(
        feat, D, nullptr, 0, W_e,                    P1,
        feat, D, nullptr, 0, W_e + (size_t)D * D,    P2,
        D, nullptr, D, 0);
    gemm_mma<<<dim3(3, 128, 2), blk, GM_SMEM>>>(
        w2v, DL, nullptr, 0, W_el,                   Q1,
        w2v, DL, nullptr, 0, W_el + (size_t)DL * DL, Q2,
        DL, nullptr, DL, 0);

    // ---- aggregation (gather, no atomics) ----
    agg_app_kernel<<<N_NODES, 256>>>(P1, P2, SP, b_e, esrc, perm, rows, AGG);
    agg_lang_kernel<<<N_NODES, 96>>>(Q1, Q2, b_el, esrc, perm, rows, AGGL);

    // ---- node updates ----
    gemm_mma<<<dim3(8, 128, 1), blk, GM_SMEM>>>(
        feat, D, AGG, D, W_nu, NF,
        feat, D, AGG, D, W_nu, NF,
        D, b_nu, D, 1);
    gemm_mma<<<dim3(3, 128, 1), blk, GM_SMEM>>>(
        w2v, DL, AGGL, DL, W_nul, NFL,
        w2v, DL, AGGL, DL, W_nul, NFL,
        DL, b_nul, DL, 1);

    // ---- predictor pre-projections (RD & RS merged via grid.z) ----
    gemm_mma<<<dim3(1, 128, 2), blk, GM_SMEM>>>(
        NF, D, NFL, DL, W_p,                                RD,
        NFL, DL, NF, D, W_p + (size_t)(D + DL + DS) * NC,   RS,
        NC, nullptr, NC, 0);

    // ---- final edge readout ----
    readout_kernel<<<NE_RO, 128>>>(RD, RS, SPRO, rsrc, rdst, pred);
}

// round 6
// speedup vs baseline: 1.1611x; 1.0157x over previous
#include <cuda_runtime.h>
#include <cstdint>
#include <cstddef>

// ---------------- problem dimensions ----------------
static constexpr int N_NODES = 16384;
static constexpr int NE      = 131072;
static constexpr int NE_RO   = 32768;
static constexpr int D       = 1024;
static constexpr int DL      = 300;
static constexpr int DS      = 16;
static constexpr int NC      = 117;

// ---------------- scratch layout ----------------
static constexpr size_t SZ_ND   = (size_t)N_NODES * D;
static constexpr size_t SZ_NDL  = (size_t)N_NODES * DL;
static constexpr size_t SZ_NC   = (size_t)N_NODES * NC;
static constexpr size_t SZ_SP   = (size_t)NE * D;
static constexpr size_t SZ_SPRO = (size_t)NE_RO * NC;

static constexpr size_t OFF_P1   = 0;
static constexpr size_t OFF_P2   = OFF_P1  + SZ_ND;
static constexpr size_t OFF_NF   = OFF_P2  + SZ_ND;
static constexpr size_t OFF_Q1   = OFF_NF  + SZ_ND;
static constexpr size_t OFF_Q2   = OFF_Q1  + SZ_NDL;
static constexpr size_t OFF_NFL  = OFF_Q2  + SZ_NDL;
static constexpr size_t OFF_RD   = OFF_NFL + SZ_NDL;
static constexpr size_t OFF_RS   = OFF_RD  + SZ_NC;
static constexpr size_t OFF_AGG  = OFF_RS  + SZ_NC;
static constexpr size_t OFF_AGGL = OFF_AGG + SZ_ND;
static constexpr size_t OFF_SPRO = OFF_AGGL + SZ_NDL;
static constexpr size_t OFF_SP   = OFF_SPRO + SZ_SPRO;
static constexpr size_t TOTAL_SCRATCH = OFF_SP + SZ_SP;

__device__ float g_scratch[TOTAL_SCRATCH];

static constexpr size_t IOFF_DEG  = 0;
static constexpr size_t IOFF_RS_  = IOFF_DEG + N_NODES;
static constexpr size_t IOFF_CUR  = IOFF_RS_ + N_NODES + 1;
static constexpr size_t IOFF_PERM = IOFF_CUR + N_NODES;
__device__ int g_iscratch[IOFF_PERM + NE];

// ---------------- CSR build kernels ----------------
__global__ void zero_int_kernel(int* __restrict__ p, int n) {
    int i = blockIdx.x * blockDim.x + threadIdx.x;
    if (i < n) p[i] = 0;
}

__global__ void hist_kernel(const int* __restrict__ edst, int* __restrict__ deg) {
    int e = blockIdx.x * blockDim.x + threadIdx.x;
    if (e < NE) atomicAdd(&deg[edst[e]], 1);
}

__global__ __launch_bounds__(512)
void scan_kernel(const int* __restrict__ deg, int* __restrict__ row_start,
                 int* __restrict__ cursor) {
    __shared__ int part[512];
    int tid = threadIdx.x;
    int base = tid * 32;
    int loc[32];
    int s = 0;
#pragma unroll
    for (int j = 0; j < 32; j++) { loc[j] = s; s += deg[base + j]; }
    part[tid] = s;
    __syncthreads();
    for (int off = 1; off < 512; off <<= 1) {
        int v = (tid >= off) ? part[tid - off] : 0;
        __syncthreads();
        part[tid] += v;
        __syncthreads();
    }
    int pre = (tid > 0) ? part[tid - 1] : 0;
#pragma unroll
    for (int j = 0; j < 32; j++) {
        int v = pre + loc[j];
        row_start[base + j] = v;
        cursor[base + j] = v;
    }
    if (tid == 511) row_start[N_NODES] = part[511];
}

__global__ void scatter_kernel(const int* __restrict__ edst, int* __restrict__ cursor,
                               int* __restrict__ perm) {
    int e = blockIdx.x * blockDim.x + threadIdx.x;
    if (e < NE) {
        int pos = atomicAdd(&cursor[edst[e]], 1);
        perm[pos] = e;
    }
}

// ---------------- bf16 split + mma + cp.async helpers ----------------
__device__ __forceinline__ void bf16_split(float f0, float f1, uint32_t& hi, uint32_t& lo) {
    uint32_t h;
    asm("cvt.rn.satfinite.bf16x2.f32 %0, %1, %2;" : "=r"(h) : "f"(f1), "f"(f0));
    float h0 = __uint_as_float(h << 16);
    float h1 = __uint_as_float(h & 0xFFFF0000u);
    float r0 = f0 - h0;
    float r1 = f1 - h1;
    uint32_t l;
    asm("cvt.rn.satfinite.bf16x2.f32 %0, %1, %2;" : "=r"(l) : "f"(r1), "f"(r0));
    hi = h; lo = l;
}

__device__ __forceinline__ void mma_bf16(float* c, const uint32_t* a, const uint32_t* b) {
    asm volatile("mma.sync.aligned.m16n8k16.row.col.f32.bf16.bf16.f32 "
        "{%0,%1,%2,%3}, {%4,%5,%6,%7}, {%8,%9}, {%0,%1,%2,%3};"
        : "+f"(c[0]), "+f"(c[1]), "+f"(c[2]), "+f"(c[3])
        : "r"(a[0]), "r"(a[1]), "r"(a[2]), "r"(a[3]), "r"(b[0]), "r"(b[1]));
}

__device__ __forceinline__ uint32_t smem_u32(const void* p) {
    uint32_t a;
    asm("{ .reg .u64 t; cvta.to.shared.u64 t, %1; cvt.u32.u64 %0, t; }" : "=r"(a) : "l"(p));
    return a;
}
__device__ __forceinline__ void cp_async16(uint32_t dst, const void* src, int src_bytes) {
    asm volatile("cp.async.cg.shared.global [%0], [%1], 16, %2;"
                 :: "r"(dst), "l"(src), "r"(src_bytes) : "memory");
}
__device__ __forceinline__ void cp_async4(uint32_t dst, const void* src, int src_bytes) {
    asm volatile("cp.async.ca.shared.global [%0], [%1], 4, %2;"
                 :: "r"(dst), "l"(src), "r"(src_bytes) : "memory");
}
#define CP_COMMIT() asm volatile("cp.async.commit_group;" ::: "memory")
#define CP_WAIT(N)  asm volatile("cp.async.wait_group %0;" :: "n"(N) : "memory")

// ---------------- bf16x3 tensor-core GEMM, cp.async 3-stage pipeline ----------------
// C = act([A1|A2] @ B + bias), B row-major [K1+K2, ldb]. grid.z selects param set.
// CTA tile 128x128, K-tile 32, 8 warps (warp tile 32x64).
static constexpr int A_PAD    = 40;
static constexpr int B_PAD    = 132;
static constexpr int A_FLTS   = 128 * A_PAD;        // 5120
static constexpr int B_FLTS   = 32 * B_PAD;         // 4224
static constexpr int BUF_FLTS = A_FLTS + B_FLTS;    // 9344
static constexpr int STAGES   = 3;
static constexpr int GM_SMEM  = STAGES * BUF_FLTS * 4;   // 112128 bytes

__global__ __launch_bounds__(256)
void gemm_mma(const float* __restrict__ A1a, int K1a, const float* __restrict__ A2a, int K2a,
              const float* __restrict__ Ba, float* __restrict__ Ca,
              const float* __restrict__ A1b, int K1b, const float* __restrict__ A2b, int K2b,
              const float* __restrict__ Bb, float* __restrict__ Cb,
              int ldb, const float* __restrict__ bias,
              int Nn, int doRelu)
{
    extern __shared__ float sm[];
    const float* A1; const float* A2; const float* B; float* Cmat; int K1, K2;
    if (blockIdx.z == 0) { A1 = A1a; K1 = K1a; A2 = A2a; K2 = K2a; B = Ba; Cmat = Ca; }
    else                 { A1 = A1b; K1 = K1b; A2 = A2b; K2 = K2b; B = Bb; Cmat = Cb; }

    const int tid  = threadIdx.x;
    const int wid  = tid >> 5;
    const int lane = tid & 31;
    const int g    = lane >> 2;
    const int t    = lane & 3;
    const int m0   = blockIdx.y * 128;
    const int n0   = blockIdx.x * 128;
    const int K    = K1 + K2;
    const int nT   = (K + 31) / 32;
    const int wm   = wid & 3;
    const int wn   = wid >> 2;
    const bool b_vec = ((ldb & 3) == 0);

    const uint32_t smb = smem_u32(sm);

    float acc[2][8][4];
#pragma unroll
    for (int i = 0; i < 2; i++)
#pragma unroll
        for (int j = 0; j < 8; j++)
#pragma unroll
            for (int k = 0; k < 4; k++) acc[i][j][k] = 0.f;

    // ---- issue async loads for tile tt into stage buf; always commits one group ----
    auto issue_load = [&](int tt, int buf) {
        if (tt < nT) {
            const int k0 = tt * 32;
            uint32_t Ab = smb + (uint32_t)buf * (BUF_FLTS * 4);
            uint32_t Bb_ = Ab + A_FLTS * 4;
#pragma unroll
            for (int i = 0; i < 4; i++) {
                int idx = i * 256 + tid;
                int row = idx >> 3, c4 = idx & 7;
                int kb = k0 + c4 * 4;
                int m  = m0 + row;
                const float* src = A1;
                int sz = 0;
                if (kb < K1)      { src = A1 + (size_t)m * K1 + kb; sz = 16; }
                else if (kb < K)  { src = A2 + (size_t)m * K2 + (kb - K1); sz = 16; }
                cp_async16(Ab + (uint32_t)(row * A_PAD + c4 * 4) * 4, src, sz);
            }
            if (b_vec) {
#pragma unroll
                for (int i = 0; i < 4; i++) {
                    int idx = i * 256 + tid;
                    int k = idx >> 5, n4 = idx & 31;
                    int kg = k0 + k;
                    int nb4 = n0 + n4 * 4;
                    const float* src = B;
                    int sz = 0;
                    if (kg < K && nb4 + 3 < Nn) { src = B + (size_t)kg * ldb + nb4; sz = 16; }
                    cp_async16(Bb_ + (uint32_t)(k * B_PAD + n4 * 4) * 4, src, sz);
                }
            } else {
#pragma unroll
                for (int i = 0; i < 4; i++) {
                    int idx = i * 256 + tid;
                    int k = idx >> 5, n4 = idx & 31;
                    int kg = k0 + k;
#pragma unroll
                    for (int j = 0; j < 4; j++) {
                        int nn = n0 + n4 * 4 + j;
                        const float* src = B;
                        int sz = 0;
                        if (kg < K && nn < Nn) { src = B + (size_t)kg * ldb + nn; sz = 4; }
                        cp_async4(Bb_ + (uint32_t)(k * B_PAD + n4 * 4 + j) * 4, src, sz);
                    }
                }
            }
        }
        CP_COMMIT();
    };

    auto compute = [&](int buf) {
        const float* As = sm + buf * BUF_FLTS + (wm * 32) * A_PAD;
        const float* Bs = sm + buf * BUF_FLTS + A_FLTS + wn * 64;
#pragma unroll
        for (int ks = 0; ks < 2; ks++) {
            uint32_t ahi[2][4], alo[2][4];
#pragma unroll
            for (int mb = 0; mb < 2; mb++) {
#pragma unroll
                for (int r = 0; r < 4; r++) {
                    int rowq = mb * 16 + g + (r & 1) * 8;
                    int kq   = ks * 16 + t * 2 + (r >> 1) * 8;
                    float2 f = *(const float2*)(As + rowq * A_PAD + kq);
                    bf16_split(f.x, f.y, ahi[mb][r], alo[mb][r]);
                }
            }
            uint32_t bhi[8][2], blo[8][2];
#pragma unroll
            for (int nb = 0; nb < 8; nb++) {
#pragma unroll
                for (int r = 0; r < 2; r++) {
                    int kq = ks * 16 + t * 2 + r * 8;
                    float f0 = Bs[kq * B_PAD + nb * 8 + g];
                    float f1 = Bs[(kq + 1) * B_PAD + nb * 8 + g];
                    bf16_split(f0, f1, bhi[nb][r], blo[nb][r]);
                }
            }
#pragma unroll
            for (int mb = 0; mb < 2; mb++) {
#pragma unroll
                for (int nb = 0; nb < 8; nb++) {
                    mma_bf16(acc[mb][nb], ahi[mb], bhi[nb]);
                    mma_bf16(acc[mb][nb], ahi[mb], blo[nb]);
                    mma_bf16(acc[mb][nb], alo[mb], bhi[nb]);
                }
            }
        }
    };

    // ---- prologue: prefetch STAGES-1 tiles ----
#pragma unroll
    for (int s = 0; s < STAGES - 1; s++) issue_load(s, s);

    // ---- main loop ----
    for (int tt = 0; tt < nT; tt++) {
        issue_load(tt + STAGES - 1, (tt + STAGES - 1) % STAGES);
        CP_WAIT(STAGES - 1);          // tile tt complete
        __syncthreads();
        compute(tt % STAGES);
        __syncthreads();              // all done reading before buffer reuse
    }

    // ---- epilogue ----
#pragma unroll
    for (int mb = 0; mb < 2; mb++) {
#pragma unroll
        for (int nb = 0; nb < 8; nb++) {
            int n = n0 + wn * 64 + nb * 8 + t * 2;
            float bv0 = 0.f, bv1 = 0.f;
            if (bias) {
                if (n     < Nn) bv0 = bias[n];
                if (n + 1 < Nn) bv1 = bias[n + 1];
            }
#pragma unroll
            for (int h = 0; h < 2; h++) {
                int m = m0 + wm * 32 + mb * 16 + g + h * 8;
                float v0 = acc[mb][nb][h * 2 + 0] + bv0;
                float v1 = acc[mb][nb][h * 2 + 1] + bv1;
                if (doRelu) { v0 = fmaxf(v0, 0.f); v1 = fmaxf(v1, 0.f); }
                float* cp = Cmat + (size_t)m * Nn + n;
                if ((Nn & 1) == 0) {
                    if (n + 1 < Nn) *(float2*)cp = make_float2(v0, v1);
                    else if (n < Nn) cp[0] = v0;
                } else {
                    if (n     < Nn) cp[0] = v0;
                    if (n + 1 < Nn) cp[1] = v1;
                }
            }
        }
    }
}

// ---------------- appearance aggregation (CSR gather) ----------------
__global__ __launch_bounds__(256)
void agg_app_kernel(const float* __restrict__ P1, const float* __restrict__ P2,
                    const float* __restrict__ SP, const float* __restrict__ b_e,
                    const int* __restrict__ esrc, const int* __restrict__ perm,
                    const int* __restrict__ row_start,
                    float* __restrict__ agg)
{
    const int n = blockIdx.x;
    const int tid = threadIdx.x;
    const int start = row_start[n];
    const int nb = row_start[n + 1] - start;

    float4 base = ((const float4*)(P2 + (size_t)n * D))[tid];
    float4 be   = ((const float4*)b_e)[tid];
    base.x += be.x; base.y += be.y; base.z += be.z; base.w += be.w;

    float4 acc = make_float4(0.f, 0.f, 0.f, 0.f);
#pragma unroll 2
    for (int i = 0; i < nb; i++) {
        int e = __ldg(&perm[start + i]);
        int s = __ldg(&esrc[e]);
        float4 v1 = ((const float4*)(P1 + (size_t)s * D))[tid];
        float4 v2 = ((const float4*)(SP + (size_t)e * D))[tid];
        acc.x += fmaxf(v1.x + v2.x + base.x, 0.f);
        acc.y += fmaxf(v1.y + v2.y + base.y, 0.f);
        acc.z += fmaxf(v1.z + v2.z + base.z, 0.f);
        acc.w += fmaxf(v1.w + v2.w + base.w, 0.f);
    }
    float inv = 1.0f / (float)max(nb, 1);
    acc.x *= inv; acc.y *= inv; acc.z *= inv; acc.w *= inv;
    ((float4*)(agg + (size_t)n * D))[tid] = acc;
}

// ---------------- language aggregation (CSR gather) ----------------
__global__ __launch_bounds__(96)
void agg_lang_kernel(const float* __restrict__ Q1, const float* __restrict__ Q2,
                     const float* __restrict__ b_el,
                     const int* __restrict__ esrc, const int* __restrict__ perm,
                     const int* __restrict__ row_start,
                     float* __restrict__ aggl)
{
    const int n = blockIdx.x;
    const int c4 = threadIdx.x;
    if (c4 >= DL / 4) return;
    const int start = row_start[n];
    const int nb = row_start[n + 1] - start;

    float4 base = ((const float4*)(Q2 + (size_t)n * DL))[c4];
    float4 be   = ((const float4*)b_el)[c4];
    base.x += be.x; base.y += be.y; base.z += be.z; base.w += be.w;

    float4 acc = make_float4(0.f, 0.f, 0.f, 0.f);
#pragma unroll 2
    for (int i = 0; i < nb; i++) {
        int e = __ldg(&perm[start + i]);
        int s = __ldg(&esrc[e]);
        float4 v = ((const float4*)(Q1 + (size_t)s * DL))[c4];
        acc.x += fmaxf(v.x + base.x, 0.f);
        acc.y += fmaxf(v.y + base.y, 0.f);
        acc.z += fmaxf(v.z + base.z, 0.f);
        acc.w += fmaxf(v.w + base.w, 0.f);
    }
    float inv = 1.0f / (float)max(nb, 1);
    acc.x *= inv; acc.y *= inv; acc.z *= inv; acc.w *= inv;
    ((float4*)(aggl + (size_t)n * DL))[c4] = acc;
}

// ---------------- readout ----------------
__global__ __launch_bounds__(128)
void readout_kernel(const float* __restrict__ Rd, const float* __restrict__ Rs,
                    const float* __restrict__ SPro,
                    const int* __restrict__ rsrc, const int* __restrict__ rdst,
                    float* __restrict__ pred)
{
    int e = blockIdx.x;
    int c = threadIdx.x;
    if (c >= NC) return;
    int s = rsrc[e];
    int d = rdst[e];
    pred[(size_t)e * NC + c] = Rd[(size_t)d * NC + c] + Rs[(size_t)s * NC + c]
                             + SPro[(size_t)e * NC + c];
}

// ---------------- host launcher ----------------
extern "C" void kernel_launch(void* const* d_in, const int* in_sizes, int n_in,
                              void* d_out, int out_size)
{
    const float* feat   = (const float*)d_in[0];
    const float* w2v    = (const float*)d_in[1];
    const float* s_f    = (const float*)d_in[2];
    const float* s_f_ro = (const float*)d_in[3];
    const float* W_e    = (const float*)d_in[4];
    const float* b_e    = (const float*)d_in[5];
    const float* W_el   = (const float*)d_in[6];
    const float* b_el   = (const float*)d_in[7];
    const float* W_nu   = (const float*)d_in[8];
    const float* b_nu   = (const float*)d_in[9];
    const float* W_nul  = (const float*)d_in[10];
    const float* b_nul  = (const float*)d_in[11];
    const float* W_p    = (const float*)d_in[12];
    const float* b_p    = (const float*)d_in[13];
    const int* esrc = (const int*)d_in[14];
    const int* edst = (const int*)d_in[15];
    const int* rsrc = (const int*)d_in[16];
    const int* rdst = (const int*)d_in[17];
    float* pred = (float*)d_out;

    float* sc = nullptr;
    cudaGetSymbolAddress((void**)&sc, g_scratch);
    int* isc = nullptr;
    cudaGetSymbolAddress((void**)&isc, g_iscratch);

    float* P1   = sc + OFF_P1;
    float* P2   = sc + OFF_P2;
    float* NF   = sc + OFF_NF;
    float* Q1   = sc + OFF_Q1;
    float* Q2   = sc + OFF_Q2;
    float* NFL  = sc + OFF_NFL;
    float* RD   = sc + OFF_RD;
    float* RS   = sc + OFF_RS;
    float* AGG  = sc + OFF_AGG;
    float* AGGL = sc + OFF_AGGL;
    float* SPRO = sc + OFF_SPRO;
    float* SP   = sc + OFF_SP;

    int* deg  = isc + IOFF_DEG;
    int* rows = isc + IOFF_RS_;
    int* cur  = isc + IOFF_CUR;
    int* perm = isc + IOFF_PERM;

    cudaFuncSetAttribute(gemm_mma, cudaFuncAttributeMaxDynamicSharedMemorySize, GM_SMEM);

    // ---- CSR build (by dst) ----
    zero_int_kernel<<<(N_NODES + 255) / 256, 256>>>(deg, N_NODES);
    hist_kernel<<<NE / 256, 256>>>(edst, deg);
    scan_kernel<<<1, 512>>>(deg, rows, cur);
    scatter_kernel<<<NE / 256, 256>>>(edst, cur, perm);

    dim3 blk(256);
    const float* Ws  = W_e + (size_t)(2 * D) * D;
    const float* Wp3 = W_p + (size_t)(D + DL) * NC;

    // ---- spatial pre-projections ----
    gemm_mma<<<dim3(8, 1024, 1), blk, GM_SMEM>>>(
        s_f, DS, nullptr, 0, Ws, SP,
        s_f, DS, nullptr, 0, Ws, SP,
        D, nullptr, D, 0);
    gemm_mma<<<dim3(1, 256, 1), blk, GM_SMEM>>>(
        s_f_ro, DS, nullptr, 0, Wp3, SPRO,
        s_f_ro, DS, nullptr, 0, Wp3, SPRO,
        NC, b_p, NC, 0);

    // ---- node-level pre-projections (siblings merged via grid.z) ----
    gemm_mma<<<dim3(8, 128, 2), blk, GM_SMEM>>>(
        feat, D, nullptr, 0, W_e,                    P1,
        feat, D, nullptr, 0, W_e + (size_t)D * D,    P2,
        D, nullptr, D, 0);
    gemm_mma<<<dim3(3, 128, 2), blk, GM_SMEM>>>(
        w2v, DL, nullptr, 0, W_el,                   Q1,
        w2v, DL, nullptr, 0, W_el + (size_t)DL * DL, Q2,
        DL, nullptr, DL, 0);

    // ---- aggregation (gather, no atomics) ----
    agg_app_kernel<<<N_NODES, 256>>>(P1, P2, SP, b_e, esrc, perm, rows, AGG);
    agg_lang_kernel<<<N_NODES, 96>>>(Q1, Q2, b_el, esrc, perm, rows, AGGL);

    // ---- node updates ----
    gemm_mma<<<dim3(8, 128, 1), blk, GM_SMEM>>>(
        feat, D, AGG, D, W_nu, NF,
        feat, D, AGG, D, W_nu, NF,
        D, b_nu, D, 1);
    gemm_mma<<<dim3(3, 128, 1), blk, GM_SMEM>>>(
        w2v, DL, AGGL, DL, W_nul, NFL,
        w2v, DL, AGGL, DL, W_nul, NFL,
        DL, b_nul, DL, 1);

    // ---- predictor pre-projections (RD & RS merged via grid.z) ----
    gemm_mma<<<dim3(1, 128, 2), blk, GM_SMEM>>>(
        NF, D, NFL, DL, W_p,                                RD,
        NFL, DL, NF, D, W_p + (size_t)(D + DL + DS) * NC,   RS,
        NC, nullptr, NC, 0);

    // ---- final edge readout ----
    readout_kernel<<<NE_RO, 128>>>(RD, RS, SPRO, rsrc, rdst, pred);
}

// round 7
// speedup vs baseline: 1.7553x; 1.5117x over previous
#include <cuda_runtime.h>
#include <cuda_fp16.h>
#include <cstdint>
#include <cstddef>

// ---------------- problem dimensions ----------------
static constexpr int N_NODES = 16384;
static constexpr int NE      = 131072;
static constexpr int NE_RO   = 32768;
static constexpr int D       = 1024;
static constexpr int DL      = 300;
static constexpr int DS      = 16;
static constexpr int NC      = 117;

// ---------------- scratch layout ----------------
static constexpr size_t SZ_ND   = (size_t)N_NODES * D;
static constexpr size_t SZ_NDL  = (size_t)N_NODES * DL;
static constexpr size_t SZ_NC   = (size_t)N_NODES * NC;
static constexpr size_t SZ_SP   = (size_t)NE * D;
static constexpr size_t SZ_SPRO = (size_t)NE_RO * NC;

static constexpr size_t OFF_P1   = 0;
static constexpr size_t OFF_P2   = OFF_P1  + SZ_ND;
static constexpr size_t OFF_NF   = OFF_P2  + SZ_ND;
static constexpr size_t OFF_Q1   = OFF_NF  + SZ_ND;
static constexpr size_t OFF_Q2   = OFF_Q1  + SZ_NDL;
static constexpr size_t OFF_NFL  = OFF_Q2  + SZ_NDL;
static constexpr size_t OFF_RD   = OFF_NFL + SZ_NDL;
static constexpr size_t OFF_RS   = OFF_RD  + SZ_NC;
static constexpr size_t OFF_AGG  = OFF_RS  + SZ_NC;
static constexpr size_t OFF_AGGL = OFF_AGG + SZ_ND;
static constexpr size_t OFF_SPRO = OFF_AGGL + SZ_NDL;
static constexpr size_t OFF_SP   = OFF_SPRO + SZ_SPRO;
static constexpr size_t TOTAL_SCRATCH = OFF_SP + SZ_SP;

__device__ float g_scratch[TOTAL_SCRATCH];

static constexpr size_t IOFF_DEG  = 0;
static constexpr size_t IOFF_RS_  = IOFF_DEG + N_NODES;
static constexpr size_t IOFF_CUR  = IOFF_RS_ + N_NODES + 1;
static constexpr size_t IOFF_PERM = IOFF_CUR + N_NODES;
__device__ int g_iscratch[IOFF_PERM + NE];

// ---------------- CSR build kernels ----------------
__global__ void zero_int_kernel(int* __restrict__ p, int n) {
    int i = blockIdx.x * blockDim.x + threadIdx.x;
    if (i < n) p[i] = 0;
}

__global__ void hist_kernel(const int* __restrict__ edst, int* __restrict__ deg) {
    int e = blockIdx.x * blockDim.x + threadIdx.x;
    if (e < NE) atomicAdd(&deg[edst[e]], 1);
}

__global__ __launch_bounds__(512)
void scan_kernel(const int* __restrict__ deg, int* __restrict__ row_start,
                 int* __restrict__ cursor) {
    __shared__ int part[512];
    int tid = threadIdx.x;
    int base = tid * 32;
    int loc[32];
    int s = 0;
#pragma unroll
    for (int j = 0; j < 32; j++) { loc[j] = s; s += deg[base + j]; }
    part[tid] = s;
    __syncthreads();
    for (int off = 1; off < 512; off <<= 1) {
        int v = (tid >= off) ? part[tid - off] : 0;
        __syncthreads();
        part[tid] += v;
        __syncthreads();
    }
    int pre = (tid > 0) ? part[tid - 1] : 0;
#pragma unroll
    for (int j = 0; j < 32; j++) {
        int v = pre + loc[j];
        row_start[base + j] = v;
        cursor[base + j] = v;
    }
    if (tid == 511) row_start[N_NODES] = part[511];
}

__global__ void scatter_kernel(const int* __restrict__ edst, int* __restrict__ cursor,
                               int* __restrict__ perm) {
    int e = blockIdx.x * blockDim.x + threadIdx.x;
    if (e < NE) {
        int pos = atomicAdd(&cursor[edst[e]], 1);
        perm[pos] = e;
    }
}

// ---------------- fp16 split + mma + cp.async helpers ----------------
__device__ __forceinline__ uint32_t f16_pack(float f0, float f1) {
    __half2 h = __floats2half2_rn(f0, f1);
    uint32_t u;
    asm("mov.b32 %0, %1;" : "=r"(u) : "r"(*(uint32_t*)&h));
    return *(uint32_t*)&h;
}
__device__ __forceinline__ void f16_split(float f0, float f1, uint32_t& hi, uint32_t& lo) {
    __half2 h = __floats2half2_rn(f0, f1);
    float2 hf = __half22float2(h);
    __half2 l = __floats2half2_rn(f0 - hf.x, f1 - hf.y);
    hi = *(uint32_t*)&h;
    lo = *(uint32_t*)&l;
}

__device__ __forceinline__ void mma_f16(float* c, const uint32_t* a, const uint32_t* b) {
    asm volatile("mma.sync.aligned.m16n8k16.row.col.f32.f16.f16.f32 "
        "{%0,%1,%2,%3}, {%4,%5,%6,%7}, {%8,%9}, {%0,%1,%2,%3};"
        : "+f"(c[0]), "+f"(c[1]), "+f"(c[2]), "+f"(c[3])
        : "r"(a[0]), "r"(a[1]), "r"(a[2]), "r"(a[3]), "r"(b[0]), "r"(b[1]));
}

__device__ __forceinline__ uint32_t smem_u32(const void* p) {
    uint32_t a;
    asm("{ .reg .u64 t; cvta.to.shared.u64 t, %1; cvt.u32.u64 %0, t; }" : "=r"(a) : "l"(p));
    return a;
}
__device__ __forceinline__ void cp_async16(uint32_t dst, const void* src, int src_bytes) {
    asm volatile("cp.async.cg.shared.global [%0], [%1], 16, %2;"
                 :: "r"(dst), "l"(src), "r"(src_bytes) : "memory");
}
__device__ __forceinline__ void cp_async4(uint32_t dst, const void* src, int src_bytes) {
    asm volatile("cp.async.ca.shared.global [%0], [%1], 4, %2;"
                 :: "r"(dst), "l"(src), "r"(src_bytes) : "memory");
}
#define CP_COMMIT() asm volatile("cp.async.commit_group;" ::: "memory")
#define CP_WAIT(N)  asm volatile("cp.async.wait_group %0;" :: "n"(N) : "memory")

// ---------------- fp16x2 tensor-core GEMM, cp.async 3-stage pipeline ----------------
// C = act([A1|A2] @ B + bias) computed as A_hi@B_h + A_lo@B_h where B_h = RN_f16(B),
// A = A_hi + A_lo (fp16 hi/lo split). Dropped term A@B_lo ~ 2^-11 relative.
// CTA tile 128x128, K-tile 32, 8 warps (warp tile 32x64).
static constexpr int A_PAD    = 40;
static constexpr int B_PAD    = 132;
static constexpr int A_FLTS   = 128 * A_PAD;
static constexpr int B_FLTS   = 32 * B_PAD;
static constexpr int BUF_FLTS = A_FLTS + B_FLTS;
static constexpr int STAGES   = 3;
static constexpr int GM_SMEM  = STAGES * BUF_FLTS * 4;   // 112128 bytes

__global__ __launch_bounds__(256)
void gemm_mma(const float* __restrict__ A1a, int K1a, const float* __restrict__ A2a, int K2a,
              const float* __restrict__ Ba, float* __restrict__ Ca,
              const float* __restrict__ A1b, int K1b, const float* __restrict__ A2b, int K2b,
              const float* __restrict__ Bb, float* __restrict__ Cb,
              int ldb, const float* __restrict__ bias,
              int Nn, int doRelu)
{
    extern __shared__ float sm[];
    const float* A1; const float* A2; const float* B; float* Cmat; int K1, K2;
    if (blockIdx.z == 0) { A1 = A1a; K1 = K1a; A2 = A2a; K2 = K2a; B = Ba; Cmat = Ca; }
    else                 { A1 = A1b; K1 = K1b; A2 = A2b; K2 = K2b; B = Bb; Cmat = Cb; }

    const int tid  = threadIdx.x;
    const int wid  = tid >> 5;
    const int lane = tid & 31;
    const int g    = lane >> 2;
    const int t    = lane & 3;
    const int m0   = blockIdx.y * 128;
    const int n0   = blockIdx.x * 128;
    const int K    = K1 + K2;
    const int nT   = (K + 31) / 32;
    const int wm   = wid & 3;
    const int wn   = wid >> 2;
    const bool b_vec = ((ldb & 3) == 0);

    const uint32_t smb = smem_u32(sm);

    float acc[2][8][4];
#pragma unroll
    for (int i = 0; i < 2; i++)
#pragma unroll
        for (int j = 0; j < 8; j++)
#pragma unroll
            for (int k = 0; k < 4; k++) acc[i][j][k] = 0.f;

    auto issue_load = [&](int tt, int buf) {
        if (tt < nT) {
            const int k0 = tt * 32;
            uint32_t Ab = smb + (uint32_t)buf * (BUF_FLTS * 4);
            uint32_t Bb_ = Ab + A_FLTS * 4;
#pragma unroll
            for (int i = 0; i < 4; i++) {
                int idx = i * 256 + tid;
                int row = idx >> 3, c4 = idx & 7;
                int kb = k0 + c4 * 4;
                int m  = m0 + row;
                const float* src = A1;
                int sz = 0;
                if (kb < K1)      { src = A1 + (size_t)m * K1 + kb; sz = 16; }
                else if (kb < K)  { src = A2 + (size_t)m * K2 + (kb - K1); sz = 16; }
                cp_async16(Ab + (uint32_t)(row * A_PAD + c4 * 4) * 4, src, sz);
            }
            if (b_vec) {
#pragma unroll
                for (int i = 0; i < 4; i++) {
                    int idx = i * 256 + tid;
                    int k = idx >> 5, n4 = idx & 31;
                    int kg = k0 + k;
                    int nb4 = n0 + n4 * 4;
                    const float* src = B;
                    int sz = 0;
                    if (kg < K && nb4 + 3 < Nn) { src = B + (size_t)kg * ldb + nb4; sz = 16; }
                    cp_async16(Bb_ + (uint32_t)(k * B_PAD + n4 * 4) * 4, src, sz);
                }
            } else {
#pragma unroll
                for (int i = 0; i < 4; i++) {
                    int idx = i * 256 + tid;
                    int k = idx >> 5, n4 = idx & 31;
                    int kg = k0 + k;
#pragma unroll
                    for (int j = 0; j < 4; j++) {
                        int nn = n0 + n4 * 4 + j;
                        const float* src = B;
                        int sz = 0;
                        if (kg < K && nn < Nn) { src = B + (size_t)kg * ldb + nn; sz = 4; }
                        cp_async4(Bb_ + (uint32_t)(k * B_PAD + n4 * 4 + j) * 4, src, sz);
                    }
                }
            }
        }
        CP_COMMIT();
    };

    auto compute = [&](int buf) {
        const float* As = sm + buf * BUF_FLTS + (wm * 32) * A_PAD;
        const float* Bs = sm + buf * BUF_FLTS + A_FLTS + wn * 64;
#pragma unroll
        for (int ks = 0; ks < 2; ks++) {
            uint32_t ahi[2][4], alo[2][4];
#pragma unroll
            for (int mb = 0; mb < 2; mb++) {
#pragma unroll
                for (int r = 0; r < 4; r++) {
                    int rowq = mb * 16 + g + (r & 1) * 8;
                    int kq   = ks * 16 + t * 2 + (r >> 1) * 8;
                    float2 f = *(const float2*)(As + rowq * A_PAD + kq);
                    f16_split(f.x, f.y, ahi[mb][r], alo[mb][r]);
                }
            }
            uint32_t bhi[8][2];
#pragma unroll
            for (int nb = 0; nb < 8; nb++) {
#pragma unroll
                for (int r = 0; r < 2; r++) {
                    int kq = ks * 16 + t * 2 + r * 8;
                    float f0 = Bs[kq * B_PAD + nb * 8 + g];
                    float f1 = Bs[(kq + 1) * B_PAD + nb * 8 + g];
                    bhi[nb][r] = f16_pack(f0, f1);
                }
            }
#pragma unroll
            for (int mb = 0; mb < 2; mb++) {
#pragma unroll
                for (int nb = 0; nb < 8; nb++) {
                    mma_f16(acc[mb][nb], ahi[mb], bhi[nb]);
                    mma_f16(acc[mb][nb], alo[mb], bhi[nb]);
                }
            }
        }
    };

    // ---- prologue: prefetch STAGES-1 tiles ----
#pragma unroll
    for (int s = 0; s < STAGES - 1; s++) issue_load(s, s);

    // ---- main loop ----
    for (int tt = 0; tt < nT; tt++) {
        issue_load(tt + STAGES - 1, (tt + STAGES - 1) % STAGES);
        CP_WAIT(STAGES - 1);
        __syncthreads();
        compute(tt % STAGES);
        __syncthreads();
    }

    // ---- epilogue ----
#pragma unroll
    for (int mb = 0; mb < 2; mb++) {
#pragma unroll
        for (int nb = 0; nb < 8; nb++) {
            int n = n0 + wn * 64 + nb * 8 + t * 2;
            float bv0 = 0.f, bv1 = 0.f;
            if (bias) {
                if (n     < Nn) bv0 = bias[n];
                if (n + 1 < Nn) bv1 = bias[n + 1];
            }
#pragma unroll
            for (int h = 0; h < 2; h++) {
                int m = m0 + wm * 32 + mb * 16 + g + h * 8;
                float v0 = acc[mb][nb][h * 2 + 0] + bv0;
                float v1 = acc[mb][nb][h * 2 + 1] + bv1;
                if (doRelu) { v0 = fmaxf(v0, 0.f); v1 = fmaxf(v1, 0.f); }
                float* cp = Cmat + (size_t)m * Nn + n;
                if ((Nn & 1) == 0) {
                    if (n + 1 < Nn) *(float2*)cp = make_float2(v0, v1);
                    else if (n < Nn) cp[0] = v0;
                } else {
                    if (n     < Nn) cp[0] = v0;
                    if (n + 1 < Nn) cp[1] = v1;
                }
            }
        }
    }
}

// ---------------- appearance aggregation (CSR gather) ----------------
__global__ __launch_bounds__(256)
void agg_app_kernel(const float* __restrict__ P1, const float* __restrict__ P2,
                    const float* __restrict__ SP, const float* __restrict__ b_e,
                    const int* __restrict__ esrc, const int* __restrict__ perm,
                    const int* __restrict__ row_start,
                    float* __restrict__ agg)
{
    const int n = blockIdx.x;
    const int tid = threadIdx.x;
    const int start = row_start[n];
    const int nb = row_start[n + 1] - start;

    float4 base = ((const float4*)(P2 + (size_t)n * D))[tid];
    float4 be   = ((const float4*)b_e)[tid];
    base.x += be.x; base.y += be.y; base.z += be.z; base.w += be.w;

    float4 acc = make_float4(0.f, 0.f, 0.f, 0.f);
#pragma unroll 2
    for (int i = 0; i < nb; i++) {
        int e = __ldg(&perm[start + i]);
        int s = __ldg(&esrc[e]);
        float4 v1 = ((const float4*)(P1 + (size_t)s * D))[tid];
        float4 v2 = ((const float4*)(SP + (size_t)e * D))[tid];
        acc.x += fmaxf(v1.x + v2.x + base.x, 0.f);
        acc.y += fmaxf(v1.y + v2.y + base.y, 0.f);
        acc.z += fmaxf(v1.z + v2.z + base.z, 0.f);
        acc.w += fmaxf(v1.w + v2.w + base.w, 0.f);
    }
    float inv = 1.0f / (float)max(nb, 1);
    acc.x *= inv; acc.y *= inv; acc.z *= inv; acc.w *= inv;
    ((float4*)(agg + (size_t)n * D))[tid] = acc;
}

// ---------------- language aggregation (CSR gather) ----------------
__global__ __launch_bounds__(96)
void agg_lang_kernel(const float* __restrict__ Q1, const float* __restrict__ Q2,
                     const float* __restrict__ b_el,
                     const int* __restrict__ esrc, const int* __restrict__ perm,
                     const int* __restrict__ row_start,
                     float* __restrict__ aggl)
{
    const int n = blockIdx.x;
    const int c4 = threadIdx.x;
    if (c4 >= DL / 4) return;
    const int start = row_start[n];
    const int nb = row_start[n + 1] - start;

    float4 base = ((const float4*)(Q2 + (size_t)n * DL))[c4];
    float4 be   = ((const float4*)b_el)[c4];
    base.x += be.x; base.y += be.y; base.z += be.z; base.w += be.w;

    float4 acc = make_float4(0.f, 0.f, 0.f, 0.f);
#pragma unroll 2
    for (int i = 0; i < nb; i++) {
        int e = __ldg(&perm[start + i]);
        int s = __ldg(&esrc[e]);
        float4 v = ((const float4*)(Q1 + (size_t)s * DL))[c4];
        acc.x += fmaxf(v.x + base.x, 0.f);
        acc.y += fmaxf(v.y + base.y, 0.f);
        acc.z += fmaxf(v.z + base.z, 0.f);
        acc.w += fmaxf(v.w + base.w, 0.f);
    }
    float inv = 1.0f / (float)max(nb, 1);
    acc.x *= inv; acc.y *= inv; acc.z *= inv; acc.w *= inv;
    ((float4*)(aggl + (size_t)n * DL))[c4] = acc;
}

// ---------------- readout ----------------
__global__ __launch_bounds__(128)
void readout_kernel(const float* __restrict__ Rd, const float* __restrict__ Rs,
                    const float* __restrict__ SPro,
                    const int* __restrict__ rsrc, const int* __restrict__ rdst,
                    float* __restrict__ pred)
{
    int e = blockIdx.x;
    int c = threadIdx.x;
    if (c >= NC) return;
    int s = rsrc[e];
    int d = rdst[e];
    pred[(size_t)e * NC + c] = Rd[(size_t)d * NC + c] + Rs[(size_t)s * NC + c]
                             + SPro[(size_t)e * NC + c];
}

// ---------------- host launcher ----------------
extern "C" void kernel_launch(void* const* d_in, const int* in_sizes, int n_in,
                              void* d_out, int out_size)
{
    const float* feat   = (const float*)d_in[0];
    const float* w2v    = (const float*)d_in[1];
    const float* s_f    = (const float*)d_in[2];
    const float* s_f_ro = (const float*)d_in[3];
    const float* W_e    = (const float*)d_in[4];
    const float* b_e    = (const float*)d_in[5];
    const float* W_el   = (const float*)d_in[6];
    const float* b_el   = (const float*)d_in[7];
    const float* W_nu   = (const float*)d_in[8];
    const float* b_nu   = (const float*)d_in[9];
    const float* W_nul  = (const float*)d_in[10];
    const float* b_nul  = (const float*)d_in[11];
    const float* W_p    = (const float*)d_in[12];
    const float* b_p    = (const float*)d_in[13];
    const int* esrc = (const int*)d_in[14];
    const int* edst = (const int*)d_in[15];
    const int* rsrc = (const int*)d_in[16];
    const int* rdst = (const int*)d_in[17];
    float* pred = (float*)d_out;

    float* sc = nullptr;
    cudaGetSymbolAddress((void**)&sc, g_scratch);
    int* isc = nullptr;
    cudaGetSymbolAddress((void**)&isc, g_iscratch);

    float* P1   = sc + OFF_P1;
    float* P2   = sc + OFF_P2;
    float* NF   = sc + OFF_NF;
    float* Q1   = sc + OFF_Q1;
    float* Q2   = sc + OFF_Q2;
    float* NFL  = sc + OFF_NFL;
    float* RD   = sc + OFF_RD;
    float* RS   = sc + OFF_RS;
    float* AGG  = sc + OFF_AGG;
    float* AGGL = sc + OFF_AGGL;
    float* SPRO = sc + OFF_SPRO;
    float* SP   = sc + OFF_SP;

    int* deg  = isc + IOFF_DEG;
    int* rows = isc + IOFF_RS_;
    int* cur  = isc + IOFF_CUR;
    int* perm = isc + IOFF_PERM;

    cudaFuncSetAttribute(gemm_mma, cudaFuncAttributeMaxDynamicSharedMemorySize, GM_SMEM);

    // ---- CSR build (by dst) ----
    zero_int_kernel<<<(N_NODES + 255) / 256, 256>>>(deg, N_NODES);
    hist_kernel<<<NE / 256, 256>>>(edst, deg);
    scan_kernel<<<1, 512>>>(deg, rows, cur);
    scatter_kernel<<<NE / 256, 256>>>(edst, cur, perm);

    dim3 blk(256);
    const float* Ws  = W_e + (size_t)(2 * D) * D;
    const float* Wp3 = W_p + (size_t)(D + DL) * NC;

    // ---- spatial pre-projections ----
    gemm_mma<<<dim3(8, 1024, 1), blk, GM_SMEM>>>(
        s_f, DS, nullptr, 0, Ws, SP,
        s_f, DS, nullptr, 0, Ws, SP,
        D, nullptr, D, 0);
    gemm_mma<<<dim3(1, 256, 1), blk, GM_SMEM>>>(
        s_f_ro, DS, nullptr, 0, Wp3, SPRO,
        s_f_ro, DS, nullptr, 0, Wp3, SPRO,
        NC, b_p, NC, 0);

    // ---- node-level pre-projections (siblings merged via grid.z) ----
    gemm_mma<<<dim3(8, 128, 2), blk, GM_SMEM>>>(
        feat, D, nullptr, 0, W_e,                    P1,
        feat, D, nullptr, 0, W_e + (size_t)D * D,    P2,
        D, nullptr, D, 0);
    gemm_mma<<<dim3(3, 128, 2), blk, GM_SMEM>>>(
        w2v, DL, nullptr, 0, W_el,                   Q1,
        w2v, DL, nullptr, 0, W_el + (size_t)DL * DL, Q2,
        DL, nullptr, DL, 0);

    // ---- aggregation (gather, no atomics) ----
    agg_app_kernel<<<N_NODES, 256>>>(P1, P2, SP, b_e, esrc, perm, rows, AGG);
    agg_lang_kernel<<<N_NODES, 96>>>(Q1, Q2, b_el, esrc, perm, rows, AGGL);

    // ---- node updates ----
    gemm_mma<<<dim3(8, 128, 1), blk, GM_SMEM>>>(
        feat, D, AGG, D, W_nu, NF,
        feat, D, AGG, D, W_nu, NF,
        D, b_nu, D, 1);
    gemm_mma<<<dim3(3, 128, 1), blk, GM_SMEM>>>(
        w2v, DL, AGGL, DL, W_nul, NFL,
        w2v, DL, AGGL, DL, W_nul, NFL,
        DL, b_nul, DL, 1);

    // ---- predictor pre-projections (RD & RS merged via grid.z) ----
    gemm_mma<<<dim3(1, 128, 2), blk, GM_SMEM>>>(
        NF, D, NFL, DL, W_p,                                RD,
        NFL, DL, NF, D, W_p + (size_t)(D + DL + DS) * NC,   RS,
        NC, nullptr, NC, 0);

    // ---- final edge readout ----
    readout_kernel<<<NE_RO, 128>>>(RD, RS, SPRO, rsrc, rdst, pred);
}

// round 8
// speedup vs baseline: 2.1203x; 1.2079x over previous
#include <cuda_runtime.h>
#include <cuda_fp16.h>
#include <cstdint>
#include <cstddef>

// ---------------- problem dimensions ----------------
static constexpr int N_NODES = 16384;
static constexpr int NE      = 131072;
static constexpr int NE_RO   = 32768;
static constexpr int D       = 1024;
static constexpr int DL      = 300;
static constexpr int DS      = 16;
static constexpr int NC      = 117;

// ---------------- scratch layout ----------------
static constexpr size_t SZ_ND   = (size_t)N_NODES * D;
static constexpr size_t SZ_NDL  = (size_t)N_NODES * DL;
static constexpr size_t SZ_NC   = (size_t)N_NODES * NC;
static constexpr size_t SZ_SP   = (size_t)NE * D;
static constexpr size_t SZ_SPRO = (size_t)NE_RO * NC;

static constexpr size_t OFF_P1   = 0;
static constexpr size_t OFF_P2   = OFF_P1  + SZ_ND;
static constexpr size_t OFF_NF   = OFF_P2  + SZ_ND;
static constexpr size_t OFF_Q1   = OFF_NF  + SZ_ND;
static constexpr size_t OFF_Q2   = OFF_Q1  + SZ_NDL;
static constexpr size_t OFF_NFL  = OFF_Q2  + SZ_NDL;
static constexpr size_t OFF_RD   = OFF_NFL + SZ_NDL;
static constexpr size_t OFF_RS   = OFF_RD  + SZ_NC;
static constexpr size_t OFF_AGG  = OFF_RS  + SZ_NC;
static constexpr size_t OFF_AGGL = OFF_AGG + SZ_ND;
static constexpr size_t OFF_SPRO = OFF_AGGL + SZ_NDL;
static constexpr size_t OFF_SP   = OFF_SPRO + SZ_SPRO;
static constexpr size_t TOTAL_SCRATCH = OFF_SP + SZ_SP;

__device__ float g_scratch[TOTAL_SCRATCH];

static constexpr size_t IOFF_DEG  = 0;
static constexpr size_t IOFF_RS_  = IOFF_DEG + N_NODES;
static constexpr size_t IOFF_CUR  = IOFF_RS_ + N_NODES + 1;
static constexpr size_t IOFF_PERM = IOFF_CUR + N_NODES;
__device__ int g_iscratch[IOFF_PERM + NE];

// ---------------- CSR build kernels ----------------
__global__ void zero_int_kernel(int* __restrict__ p, int n) {
    int i = blockIdx.x * blockDim.x + threadIdx.x;
    if (i < n) p[i] = 0;
}

__global__ void hist_kernel(const int* __restrict__ edst, int* __restrict__ deg) {
    int e = blockIdx.x * blockDim.x + threadIdx.x;
    if (e < NE) atomicAdd(&deg[edst[e]], 1);
}

__global__ __launch_bounds__(512)
void scan_kernel(const int* __restrict__ deg, int* __restrict__ row_start,
                 int* __restrict__ cursor) {
    __shared__ int part[512];
    int tid = threadIdx.x;
    int base = tid * 32;
    int loc[32];
    int s = 0;
#pragma unroll
    for (int j = 0; j < 32; j++) { loc[j] = s; s += deg[base + j]; }
    part[tid] = s;
    __syncthreads();
    for (int off = 1; off < 512; off <<= 1) {
        int v = (tid >= off) ? part[tid - off] : 0;
        __syncthreads();
        part[tid] += v;
        __syncthreads();
    }
    int pre = (tid > 0) ? part[tid - 1] : 0;
#pragma unroll
    for (int j = 0; j < 32; j++) {
        int v = pre + loc[j];
        row_start[base + j] = v;
        cursor[base + j] = v;
    }
    if (tid == 511) row_start[N_NODES] = part[511];
}

__global__ void scatter_kernel(const int* __restrict__ edst, int* __restrict__ cursor,
                               int* __restrict__ perm) {
    int e = blockIdx.x * blockDim.x + threadIdx.x;
    if (e < NE) {
        int pos = atomicAdd(&cursor[edst[e]], 1);
        perm[pos] = e;
    }
}

// ---------------- fp16 pack + mma + cp.async helpers ----------------
__device__ __forceinline__ uint32_t f16_pack(float f0, float f1) {
    __half2 h = __floats2half2_rn(f0, f1);
    return *(uint32_t*)&h;
}

__device__ __forceinline__ void mma_f16(float* c, const uint32_t* a, const uint32_t* b) {
    asm volatile("mma.sync.aligned.m16n8k16.row.col.f32.f16.f16.f32 "
        "{%0,%1,%2,%3}, {%4,%5,%6,%7}, {%8,%9}, {%0,%1,%2,%3};"
        : "+f"(c[0]), "+f"(c[1]), "+f"(c[2]), "+f"(c[3])
        : "r"(a[0]), "r"(a[1]), "r"(a[2]), "r"(a[3]), "r"(b[0]), "r"(b[1]));
}

__device__ __forceinline__ uint32_t smem_u32(const void* p) {
    uint32_t a;
    asm("{ .reg .u64 t; cvta.to.shared.u64 t, %1; cvt.u32.u64 %0, t; }" : "=r"(a) : "l"(p));
    return a;
}
__device__ __forceinline__ void cp_async16(uint32_t dst, const void* src, int src_bytes) {
    asm volatile("cp.async.cg.shared.global [%0], [%1], 16, %2;"
                 :: "r"(dst), "l"(src), "r"(src_bytes) : "memory");
}
__device__ __forceinline__ void cp_async4(uint32_t dst, const void* src, int src_bytes) {
    asm volatile("cp.async.ca.shared.global [%0], [%1], 4, %2;"
                 :: "r"(dst), "l"(src), "r"(src_bytes) : "memory");
}
#define CP_COMMIT() asm volatile("cp.async.commit_group;" ::: "memory")
#define CP_WAIT(N)  asm volatile("cp.async.wait_group %0;" :: "n"(N) : "memory")

// ---------------- fp16 tensor-core GEMM, cp.async 3-stage pipeline ----------------
// C = act([A1|A2] @ B + bias) computed as RN16(A) @ RN16(B) with fp32 accum.
// CTA tile 128x128, K-tile 32, 8 warps (warp tile 32x64).
static constexpr int A_PAD    = 40;
static constexpr int B_PAD    = 132;
static constexpr int A_FLTS   = 128 * A_PAD;
static constexpr int B_FLTS   = 32 * B_PAD;
static constexpr int BUF_FLTS = A_FLTS + B_FLTS;
static constexpr int STAGES   = 3;
static constexpr int GM_SMEM  = STAGES * BUF_FLTS * 4;   // 112128 bytes

__global__ __launch_bounds__(256)
void gemm_mma(const float* __restrict__ A1a, int K1a, const float* __restrict__ A2a, int K2a,
              const float* __restrict__ Ba, float* __restrict__ Ca,
              const float* __restrict__ A1b, int K1b, const float* __restrict__ A2b, int K2b,
              const float* __restrict__ Bb, float* __restrict__ Cb,
              int ldb, const float* __restrict__ bias,
              int Nn, int doRelu)
{
    extern __shared__ float sm[];
    const float* A1; const float* A2; const float* B; float* Cmat; int K1, K2;
    if (blockIdx.z == 0) { A1 = A1a; K1 = K1a; A2 = A2a; K2 = K2a; B = Ba; Cmat = Ca; }
    else                 { A1 = A1b; K1 = K1b; A2 = A2b; K2 = K2b; B = Bb; Cmat = Cb; }

    const int tid  = threadIdx.x;
    const int wid  = tid >> 5;
    const int lane = tid & 31;
    const int g    = lane >> 2;
    const int t    = lane & 3;
    const int m0   = blockIdx.y * 128;
    const int n0   = blockIdx.x * 128;
    const int K    = K1 + K2;
    const int nT   = (K + 31) / 32;
    const int wm   = wid & 3;
    const int wn   = wid >> 2;
    const bool b_vec = ((ldb & 3) == 0);

    const uint32_t smb = smem_u32(sm);

    float acc[2][8][4];
#pragma unroll
    for (int i = 0; i < 2; i++)
#pragma unroll
        for (int j = 0; j < 8; j++)
#pragma unroll
            for (int k = 0; k < 4; k++) acc[i][j][k] = 0.f;

    auto issue_load = [&](int tt, int buf) {
        if (tt < nT) {
            const int k0 = tt * 32;
            uint32_t Ab = smb + (uint32_t)buf * (BUF_FLTS * 4);
            uint32_t Bb_ = Ab + A_FLTS * 4;
#pragma unroll
            for (int i = 0; i < 4; i++) {
                int idx = i * 256 + tid;
                int row = idx >> 3, c4 = idx & 7;
                int kb = k0 + c4 * 4;
                int m  = m0 + row;
                const float* src = A1;
                int sz = 0;
                if (kb < K1)      { src = A1 + (size_t)m * K1 + kb; sz = 16; }
                else if (kb < K)  { src = A2 + (size_t)m * K2 + (kb - K1); sz = 16; }
                cp_async16(Ab + (uint32_t)(row * A_PAD + c4 * 4) * 4, src, sz);
            }
            if (b_vec) {
#pragma unroll
                for (int i = 0; i < 4; i++) {
                    int idx = i * 256 + tid;
                    int k = idx >> 5, n4 = idx & 31;
                    int kg = k0 + k;
                    int nb4 = n0 + n4 * 4;
                    const float* src = B;
                    int sz = 0;
                    if (kg < K && nb4 + 3 < Nn) { src = B + (size_t)kg * ldb + nb4; sz = 16; }
                    cp_async16(Bb_ + (uint32_t)(k * B_PAD + n4 * 4) * 4, src, sz);
                }
            } else {
#pragma unroll
                for (int i = 0; i < 4; i++) {
                    int idx = i * 256 + tid;
                    int k = idx >> 5, n4 = idx & 31;
                    int kg = k0 + k;
#pragma unroll
                    for (int j = 0; j < 4; j++) {
                        int nn = n0 + n4 * 4 + j;
                        const float* src = B;
                        int sz = 0;
                        if (kg < K && nn < Nn) { src = B + (size_t)kg * ldb + nn; sz = 4; }
                        cp_async4(Bb_ + (uint32_t)(k * B_PAD + n4 * 4 + j) * 4, src, sz);
                    }
                }
            }
        }
        CP_COMMIT();
    };

    auto compute = [&](int buf) {
        const float* As = sm + buf * BUF_FLTS + (wm * 32) * A_PAD;
        const float* Bs = sm + buf * BUF_FLTS + A_FLTS + wn * 64;
#pragma unroll
        for (int ks = 0; ks < 2; ks++) {
            uint32_t ah[2][4];
#pragma unroll
            for (int mb = 0; mb < 2; mb++) {
#pragma unroll
                for (int r = 0; r < 4; r++) {
                    int rowq = mb * 16 + g + (r & 1) * 8;
                    int kq   = ks * 16 + t * 2 + (r >> 1) * 8;
                    float2 f = *(const float2*)(As + rowq * A_PAD + kq);
                    ah[mb][r] = f16_pack(f.x, f.y);
                }
            }
            uint32_t bh[8][2];
#pragma unroll
            for (int nb = 0; nb < 8; nb++) {
#pragma unroll
                for (int r = 0; r < 2; r++) {
                    int kq = ks * 16 + t * 2 + r * 8;
                    float f0 = Bs[kq * B_PAD + nb * 8 + g];
                    float f1 = Bs[(kq + 1) * B_PAD + nb * 8 + g];
                    bh[nb][r] = f16_pack(f0, f1);
                }
            }
#pragma unroll
            for (int mb = 0; mb < 2; mb++) {
#pragma unroll
                for (int nb = 0; nb < 8; nb++) {
                    mma_f16(acc[mb][nb], ah[mb], bh[nb]);
                }
            }
        }
    };

    // ---- prologue: prefetch STAGES-1 tiles ----
#pragma unroll
    for (int s = 0; s < STAGES - 1; s++) issue_load(s, s);

    // ---- main loop ----
    for (int tt = 0; tt < nT; tt++) {
        issue_load(tt + STAGES - 1, (tt + STAGES - 1) % STAGES);
        CP_WAIT(STAGES - 1);
        __syncthreads();
        compute(tt % STAGES);
        __syncthreads();
    }

    // ---- epilogue ----
#pragma unroll
    for (int mb = 0; mb < 2; mb++) {
#pragma unroll
        for (int nb = 0; nb < 8; nb++) {
            int n = n0 + wn * 64 + nb * 8 + t * 2;
            float bv0 = 0.f, bv1 = 0.f;
            if (bias) {
                if (n     < Nn) bv0 = bias[n];
                if (n + 1 < Nn) bv1 = bias[n + 1];
            }
#pragma unroll
            for (int h = 0; h < 2; h++) {
                int m = m0 + wm * 32 + mb * 16 + g + h * 8;
                float v0 = acc[mb][nb][h * 2 + 0] + bv0;
                float v1 = acc[mb][nb][h * 2 + 1] + bv1;
                if (doRelu) { v0 = fmaxf(v0, 0.f); v1 = fmaxf(v1, 0.f); }
                float* cp = Cmat + (size_t)m * Nn + n;
                if ((Nn & 1) == 0) {
                    if (n + 1 < Nn) *(float2*)cp = make_float2(v0, v1);
                    else if (n < Nn) cp[0] = v0;
                } else {
                    if (n     < Nn) cp[0] = v0;
                    if (n + 1 < Nn) cp[1] = v1;
                }
            }
        }
    }
}

// ---------------- appearance aggregation (CSR gather) ----------------
__global__ __launch_bounds__(256)
void agg_app_kernel(const float* __restrict__ P1, const float* __restrict__ P2,
                    const float* __restrict__ SP, const float* __restrict__ b_e,
                    const int* __restrict__ esrc, const int* __restrict__ perm,
                    const int* __restrict__ row_start,
                    float* __restrict__ agg)
{
    const int n = blockIdx.x;
    const int tid = threadIdx.x;
    const int start = row_start[n];
    const int nb = row_start[n + 1] - start;

    float4 base = ((const float4*)(P2 + (size_t)n * D))[tid];
    float4 be   = ((const float4*)b_e)[tid];
    base.x += be.x; base.y += be.y; base.z += be.z; base.w += be.w;

    float4 acc = make_float4(0.f, 0.f, 0.f, 0.f);
#pragma unroll 2
    for (int i = 0; i < nb; i++) {
        int e = __ldg(&perm[start + i]);
        int s = __ldg(&esrc[e]);
        float4 v1 = ((const float4*)(P1 + (size_t)s * D))[tid];
        float4 v2 = ((const float4*)(SP + (size_t)e * D))[tid];
        acc.x += fmaxf(v1.x + v2.x + base.x, 0.f);
        acc.y += fmaxf(v1.y + v2.y + base.y, 0.f);
        acc.z += fmaxf(v1.z + v2.z + base.z, 0.f);
        acc.w += fmaxf(v1.w + v2.w + base.w, 0.f);
    }
    float inv = 1.0f / (float)max(nb, 1);
    acc.x *= inv; acc.y *= inv; acc.z *= inv; acc.w *= inv;
    ((float4*)(agg + (size_t)n * D))[tid] = acc;
}

// ---------------- language aggregation (CSR gather) ----------------
__global__ __launch_bounds__(96)
void agg_lang_kernel(const float* __restrict__ Q1, const float* __restrict__ Q2,
                     const float* __restrict__ b_el,
                     const int* __restrict__ esrc, const int* __restrict__ perm,
                     const int* __restrict__ row_start,
                     float* __restrict__ aggl)
{
    const int n = blockIdx.x;
    const int c4 = threadIdx.x;
    if (c4 >= DL / 4) return;
    const int start = row_start[n];
    const int nb = row_start[n + 1] - start;

    float4 base = ((const float4*)(Q2 + (size_t)n * DL))[c4];
    float4 be   = ((const float4*)b_el)[c4];
    base.x += be.x; base.y += be.y; base.z += be.z; base.w += be.w;

    float4 acc = make_float4(0.f, 0.f, 0.f, 0.f);
#pragma unroll 2
    for (int i = 0; i < nb; i++) {
        int e = __ldg(&perm[start + i]);
        int s = __ldg(&esrc[e]);
        float4 v = ((const float4*)(Q1 + (size_t)s * DL))[c4];
        acc.x += fmaxf(v.x + base.x, 0.f);
        acc.y += fmaxf(v.y + base.y, 0.f);
        acc.z += fmaxf(v.z + base.z, 0.f);
        acc.w += fmaxf(v.w + base.w, 0.f);
    }
    float inv = 1.0f / (float)max(nb, 1);
    acc.x *= inv; acc.y *= inv; acc.z *= inv; acc.w *= inv;
    ((float4*)(aggl + (size_t)n * DL))[c4] = acc;
}

// ---------------- readout ----------------
__global__ __launch_bounds__(128)
void readout_kernel(const float* __restrict__ Rd, const float* __restrict__ Rs,
                    const float* __restrict__ SPro,
                    const int* __restrict__ rsrc, const int* __restrict__ rdst,
                    float* __restrict__ pred)
{
    int e = blockIdx.x;
    int c = threadIdx.x;
    if (c >= NC) return;
    int s = rsrc[e];
    int d = rdst[e];
    pred[(size_t)e * NC + c] = Rd[(size_t)d * NC + c] + Rs[(size_t)s * NC + c]
                             + SPro[(size_t)e * NC + c];
}

// ---------------- host launcher ----------------
extern "C" void kernel_launch(void* const* d_in, const int* in_sizes, int n_in,
                              void* d_out, int out_size)
{
    const float* feat   = (const float*)d_in[0];
    const float* w2v    = (const float*)d_in[1];
    const float* s_f    = (const float*)d_in[2];
    const float* s_f_ro = (const float*)d_in[3];
    const float* W_e    = (const float*)d_in[4];
    const float* b_e    = (const float*)d_in[5];
    const float* W_el   = (const float*)d_in[6];
    const float* b_el   = (const float*)d_in[7];
    const float* W_nu   = (const float*)d_in[8];
    const float* b_nu   = (const float*)d_in[9];
    const float* W_nul  = (const float*)d_in[10];
    const float* b_nul  = (const float*)d_in[11];
    const float* W_p    = (const float*)d_in[12];
    const float* b_p    = (const float*)d_in[13];
    const int* esrc = (const int*)d_in[14];
    const int* edst = (const int*)d_in[15];
    const int* rsrc = (const int*)d_in[16];
    const int* rdst = (const int*)d_in[17];
    float* pred = (float*)d_out;

    float* sc = nullptr;
    cudaGetSymbolAddress((void**)&sc, g_scratch);
    int* isc = nullptr;
    cudaGetSymbolAddress((void**)&isc, g_iscratch);

    float* P1   = sc + OFF_P1;
    float* P2   = sc + OFF_P2;
    float* NF   = sc + OFF_NF;
    float* Q1   = sc + OFF_Q1;
    float* Q2   = sc + OFF_Q2;
    float* NFL  = sc + OFF_NFL;
    float* RD   = sc + OFF_RD;
    float* RS   = sc + OFF_RS;
    float* AGG  = sc + OFF_AGG;
    float* AGGL = sc + OFF_AGGL;
    float* SPRO = sc + OFF_SPRO;
    float* SP   = sc + OFF_SP;

    int* deg  = isc + IOFF_DEG;
    int* rows = isc + IOFF_RS_;
    int* cur  = isc + IOFF_CUR;
    int* perm = isc + IOFF_PERM;

    cudaFuncSetAttribute(gemm_mma, cudaFuncAttributeMaxDynamicSharedMemorySize, GM_SMEM);

    // ---- CSR build (by dst) ----
    zero_int_kernel<<<(N_NODES + 255) / 256, 256>>>(deg, N_NODES);
    hist_kernel<<<NE / 256, 256>>>(edst, deg);
    scan_kernel<<<1, 512>>>(deg, rows, cur);
    scatter_kernel<<<NE / 256, 256>>>(edst, cur, perm);

    dim3 blk(256);
    const float* Ws  = W_e + (size_t)(2 * D) * D;
    const float* Wp3 = W_p + (size_t)(D + DL) * NC;

    // ---- spatial pre-projections ----
    gemm_mma<<<dim3(8, 1024, 1), blk, GM_SMEM>>>(
        s_f, DS, nullptr, 0, Ws, SP,
        s_f, DS, nullptr, 0, Ws, SP,
        D, nullptr, D, 0);
    gemm_mma<<<dim3(1, 256, 1), blk, GM_SMEM>>>(
        s_f_ro, DS, nullptr, 0, Wp3, SPRO,
        s_f_ro, DS, nullptr, 0, Wp3, SPRO,
        NC, b_p, NC, 0);

    // ---- node-level pre-projections (siblings merged via grid.z) ----
    gemm_mma<<<dim3(8, 128, 2), blk, GM_SMEM>>>(
        feat, D, nullptr, 0, W_e,                    P1,
        feat, D, nullptr, 0, W_e + (size_t)D * D,    P2,
        D, nullptr, D, 0);
    gemm_mma<<<dim3(3, 128, 2), blk, GM_SMEM>>>(
        w2v, DL, nullptr, 0, W_el,                   Q1,
        w2v, DL, nullptr, 0, W_el + (size_t)DL * DL, Q2,
        DL, nullptr, DL, 0);

    // ---- aggregation (gather, no atomics) ----
    agg_app_kernel<<<N_NODES, 256>>>(P1, P2, SP, b_e, esrc, perm, rows, AGG);
    agg_lang_kernel<<<N_NODES, 96>>>(Q1, Q2, b_el, esrc, perm, rows, AGGL);

    // ---- node updates ----
    gemm_mma<<<dim3(8, 128, 1), blk, GM_SMEM>>>(
        feat, D, AGG, D, W_nu, NF,
        feat, D, AGG, D, W_nu, NF,
        D, b_nu, D, 1);
    gemm_mma<<<dim3(3, 128, 1), blk, GM_SMEM>>>(
        w2v, DL, AGGL, DL, W_nul, NFL,
        w2v, DL, AGGL, DL, W_nul, NFL,
        DL, b_nul, DL, 1);

    // ---- predictor pre-projections (RD & RS merged via grid.z) ----
    gemm_mma<<<dim3(1, 128, 2), blk, GM_SMEM>>>(
        NF, D, NFL, DL, W_p,                                RD,
        NFL, DL, NF, D, W_p + (size_t)(D + DL + DS) * NC,   RS,
        NC, nullptr, NC, 0);

    // ---- final edge readout ----
    readout_kernel<<<NE_RO, 128>>>(RD, RS, SPRO, rsrc, rdst, pred);
}

// round 9
// speedup vs baseline: 2.3873x; 1.1259x over previous
#include <cuda_runtime.h>
#include <cuda_fp16.h>
#include <cstdint>
#include <cstddef>

// ---------------- problem dimensions ----------------
static constexpr int N_NODES = 16384;
static constexpr int NE      = 131072;
static constexpr int NE_RO   = 32768;
static constexpr int D       = 1024;
static constexpr int DL      = 300;
static constexpr int DS      = 16;
static constexpr int NC      = 117;

// ---------------- fp32 scratch (readout precursors) ----------------
static constexpr size_t SZ_NC   = (size_t)N_NODES * NC;
static constexpr size_t SZ_SPRO = (size_t)NE_RO * NC;
static constexpr size_t OFF_RD   = 0;
static constexpr size_t OFF_RS   = OFF_RD + SZ_NC;
static constexpr size_t OFF_SPRO = OFF_RS + SZ_NC;
static constexpr size_t TOTAL_F32 = OFF_SPRO + SZ_SPRO;
__device__ float g_scratch[TOTAL_F32];

// ---------------- fp16 scratch ----------------
// FA  [N][2048]  = [feat | AGG]
// WA  [N][608]   = [w2v | AGGL | pad4..8]
// NFA [N][1328]  = [NF | NFL | pad4]
static constexpr size_t HOFF_FA   = 0;
static constexpr size_t HSZ_FA    = (size_t)N_NODES * 2048;
static constexpr size_t HOFF_WA   = HOFF_FA + HSZ_FA;
static constexpr size_t HSZ_WA    = (size_t)N_NODES * 608;
static constexpr size_t HOFF_NFA  = HOFF_WA + HSZ_WA;
static constexpr size_t HSZ_NFA   = (size_t)N_NODES * 1328;
static constexpr size_t HOFF_P1   = HOFF_NFA + HSZ_NFA;
static constexpr size_t HSZ_P     = (size_t)N_NODES * 1024;
static constexpr size_t HOFF_P2   = HOFF_P1 + HSZ_P;
static constexpr size_t HOFF_Q1   = HOFF_P2 + HSZ_P;
static constexpr size_t HSZ_Q     = (size_t)N_NODES * 304;
static constexpr size_t HOFF_Q2   = HOFF_Q1 + HSZ_Q;
static constexpr size_t HOFF_SP   = HOFF_Q2 + HSZ_Q;
static constexpr size_t HSZ_SP    = (size_t)NE * 1024;
static constexpr size_t HOFF_SFH  = HOFF_SP + HSZ_SP;
static constexpr size_t HSZ_SFH   = (size_t)NE * 16;
static constexpr size_t HOFF_SFRO = HOFF_SFH + HSZ_SFH;
static constexpr size_t HSZ_SFRO  = (size_t)NE_RO * 16;
static constexpr size_t TOTAL_H   = HOFF_SFRO + HSZ_SFRO;
__device__ __half g_hscratch[TOTAL_H];

// int scratch: deg, row_start, cursor, perm
static constexpr size_t IOFF_DEG  = 0;
static constexpr size_t IOFF_RS_  = IOFF_DEG + N_NODES;
static constexpr size_t IOFF_CUR  = IOFF_RS_ + N_NODES + 1;
static constexpr size_t IOFF_PERM = IOFF_CUR + N_NODES;
__device__ int g_iscratch[IOFF_PERM + NE];

// ---------------- CSR build kernels ----------------
__global__ void zero_int_kernel(int* __restrict__ p, int n) {
    int i = blockIdx.x * blockDim.x + threadIdx.x;
    if (i < n) p[i] = 0;
}

__global__ void hist_kernel(const int* __restrict__ edst, int* __restrict__ deg) {
    int e = blockIdx.x * blockDim.x + threadIdx.x;
    if (e < NE) atomicAdd(&deg[edst[e]], 1);
}

__global__ __launch_bounds__(512)
void scan_kernel(const int* __restrict__ deg, int* __restrict__ row_start,
                 int* __restrict__ cursor) {
    __shared__ int part[512];
    int tid = threadIdx.x;
    int base = tid * 32;
    int loc[32];
    int s = 0;
#pragma unroll
    for (int j = 0; j < 32; j++) { loc[j] = s; s += deg[base + j]; }
    part[tid] = s;
    __syncthreads();
    for (int off = 1; off < 512; off <<= 1) {
        int v = (tid >= off) ? part[tid - off] : 0;
        __syncthreads();
        part[tid] += v;
        __syncthreads();
    }
    int pre = (tid > 0) ? part[tid - 1] : 0;
#pragma unroll
    for (int j = 0; j < 32; j++) {
        int v = pre + loc[j];
        row_start[base + j] = v;
        cursor[base + j] = v;
    }
    if (tid == 511) row_start[N_NODES] = part[511];
}

__global__ void scatter_kernel(const int* __restrict__ edst, int* __restrict__ cursor,
                               int* __restrict__ perm) {
    int e = blockIdx.x * blockDim.x + threadIdx.x;
    if (e < NE) {
        int pos = atomicAdd(&cursor[edst[e]], 1);
        perm[pos] = e;
    }
}

// ---------------- conversion kernels ----------------
__global__ __launch_bounds__(256)
void conv_node_kernel(const float* __restrict__ feat, const float* __restrict__ w2v,
                      __half* __restrict__ FA, __half* __restrict__ WA,
                      __half* __restrict__ NFA)
{
    int n = blockIdx.x, tid = threadIdx.x;
    // feat -> FA cols 0..1023
    float4 f = *(const float4*)(feat + (size_t)n * 1024 + tid * 4);
    __half2 h0 = __floats2half2_rn(f.x, f.y);
    __half2 h1 = __floats2half2_rn(f.z, f.w);
    uint2 u; u.x = *(uint32_t*)&h0; u.y = *(uint32_t*)&h1;
    *(uint2*)(FA + (size_t)n * 2048 + tid * 4) = u;
    if (tid < 75) {
        float4 w = *(const float4*)(w2v + (size_t)n * 300 + tid * 4);
        __half2 g0 = __floats2half2_rn(w.x, w.y);
        __half2 g1 = __floats2half2_rn(w.z, w.w);
        uint2 v; v.x = *(uint32_t*)&g0; v.y = *(uint32_t*)&g1;
        *(uint2*)(WA + (size_t)n * 608 + tid * 4) = v;
    } else if (tid == 75) {
        uint2 z = make_uint2(0, 0);
        *(uint2*)(WA + (size_t)n * 608 + 600) = z;
        *(uint2*)(WA + (size_t)n * 608 + 604) = z;
    } else if (tid == 76) {
        uint2 z = make_uint2(0, 0);
        *(uint2*)(NFA + (size_t)n * 1328 + 1324) = z;
    }
}

__global__ void conv_sf_kernel(const float* __restrict__ s_f, const float* __restrict__ s_f_ro,
                               __half* __restrict__ sfh, __half* __restrict__ sfroh)
{
    size_t i = (size_t)blockIdx.x * blockDim.x + threadIdx.x;   // pair index
    size_t n1 = (size_t)NE * 8;
    size_t tot = n1 + (size_t)NE_RO * 8;
    if (i >= tot) return;
    if (i < n1) {
        float2 f = *(const float2*)(s_f + i * 2);
        __half2 h = __floats2half2_rn(f.x, f.y);
        *(uint32_t*)(sfh + i * 2) = *(uint32_t*)&h;
    } else {
        size_t j = i - n1;
        float2 f = *(const float2*)(s_f_ro + j * 2);
        __half2 h = __floats2half2_rn(f.x, f.y);
        *(uint32_t*)(sfroh + j * 2) = *(uint32_t*)&h;
    }
}

// ---------------- mma + cp.async helpers ----------------
__device__ __forceinline__ uint32_t f16_pack(float f0, float f1) {
    __half2 h = __floats2half2_rn(f0, f1);
    return *(uint32_t*)&h;
}

__device__ __forceinline__ void mma_f16(float* c, const uint32_t* a, const uint32_t* b) {
    asm volatile("mma.sync.aligned.m16n8k16.row.col.f32.f16.f16.f32 "
        "{%0,%1,%2,%3}, {%4,%5,%6,%7}, {%8,%9}, {%0,%1,%2,%3};"
        : "+f"(c[0]), "+f"(c[1]), "+f"(c[2]), "+f"(c[3])
        : "r"(a[0]), "r"(a[1]), "r"(a[2]), "r"(a[3]), "r"(b[0]), "r"(b[1]));
}

__device__ __forceinline__ uint32_t smem_u32(const void* p) {
    uint32_t a;
    asm("{ .reg .u64 t; cvta.to.shared.u64 t, %1; cvt.u32.u64 %0, t; }" : "=r"(a) : "l"(p));
    return a;
}
__device__ __forceinline__ void cp_async16(uint32_t dst, const void* src, int src_bytes) {
    asm volatile("cp.async.cg.shared.global [%0], [%1], 16, %2;"
                 :: "r"(dst), "l"(src), "r"(src_bytes) : "memory");
}
__device__ __forceinline__ void cp_async4(uint32_t dst, const void* src, int src_bytes) {
    asm volatile("cp.async.ca.shared.global [%0], [%1], 4, %2;"
                 :: "r"(dst), "l"(src), "r"(src_bytes) : "memory");
}
#define CP_COMMIT() asm volatile("cp.async.commit_group;" ::: "memory")
#define CP_WAIT(N)  asm volatile("cp.async.wait_group %0;" :: "n"(N) : "memory")

// ---------------- fp16-A GEMM, cp.async 3-stage pipeline ----------------
// C = act(A_h @ B + bias); A fp16 [M, lda], B fp32 two-row-segment:
//   row kg -> (kg < KB1) ? B1[kg] : B2[kg-KB1]    (row stride ldb)
// grid.z selects GArgs set. Output fp16 (ldc) or fp32 (ldc).
struct GArgs {
    const __half* A; int lda; int K;
    const float* B1; const float* B2; int KB1;
    void* C; int ldc;
};

static constexpr int A_PAD_H   = 40;                       // halves per A row
static constexpr int A_BYTES   = 128 * A_PAD_H * 2;        // 10240
static constexpr int B_PAD     = 132;                      // floats per B row
static constexpr int B_BYTES   = 32 * B_PAD * 4;           // 16896
static constexpr int STG_BYTES = A_BYTES + B_BYTES;        // 27136
static constexpr int STAGES    = 3;
static constexpr int GM_SMEM   = STAGES * STG_BYTES;       // 81408

__global__ __launch_bounds__(256)
void gemm_h(GArgs za, GArgs zb, int ldb, const float* __restrict__ bias,
            int Nn, int doRelu, int outHalf)
{
    extern __shared__ char smc[];
    GArgs ga = (blockIdx.z == 0) ? za : zb;

    const int tid  = threadIdx.x;
    const int wid  = tid >> 5;
    const int lane = tid & 31;
    const int g    = lane >> 2;
    const int t    = lane & 3;
    const int m0   = blockIdx.y * 128;
    const int n0   = blockIdx.x * 128;
    const int K    = ga.K;
    const int nT   = (K + 31) / 32;
    const int wm   = wid & 3;
    const int wn   = wid >> 2;
    const bool b_vec = ((ldb & 3) == 0);

    const uint32_t smb = smem_u32(smc);

    float acc[2][8][4];
#pragma unroll
    for (int i = 0; i < 2; i++)
#pragma unroll
        for (int j = 0; j < 8; j++)
#pragma unroll
            for (int k = 0; k < 4; k++) acc[i][j][k] = 0.f;

    auto issue_load = [&](int tt, int buf) {
        if (tt < nT) {
            const int k0 = tt * 32;
            uint32_t Ab = smb + (uint32_t)buf * STG_BYTES;
            uint32_t Bb = Ab + A_BYTES;
            // A: 512 chunks of 8 halves, 2 per thread
#pragma unroll
            for (int i = 0; i < 2; i++) {
                int idx = i * 256 + tid;
                int row = idx >> 2, c8 = idx & 3;
                int kb = k0 + c8 * 8;
                const __half* src = ga.A;
                int sz = 0;
                if (kb < K) { src = ga.A + (size_t)(m0 + row) * ga.lda + kb; sz = 16; }
                cp_async16(Ab + (uint32_t)(row * (A_PAD_H * 2) + c8 * 16), src, sz);
            }
            // B: fp32 [32][128], two row segments
            if (b_vec) {
#pragma unroll
                for (int i = 0; i < 4; i++) {
                    int idx = i * 256 + tid;
                    int k = idx >> 5, n4 = idx & 31;
                    int kg = k0 + k;
                    int nb4 = n0 + n4 * 4;
                    const float* src = ga.B1;
                    int sz = 0;
                    if (kg < K && nb4 + 3 < Nn) {
                        src = (kg < ga.KB1) ? (ga.B1 + (size_t)kg * ldb + nb4)
                                            : (ga.B2 + (size_t)(kg - ga.KB1) * ldb + nb4);
                        sz = 16;
                    }
                    cp_async16(Bb + (uint32_t)(k * B_PAD + n4 * 4) * 4, src, sz);
                }
            } else {
#pragma unroll
                for (int i = 0; i < 4; i++) {
                    int idx = i * 256 + tid;
                    int k = idx >> 5, n4 = idx & 31;
                    int kg = k0 + k;
#pragma unroll
                    for (int j = 0; j < 4; j++) {
                        int nn = n0 + n4 * 4 + j;
                        const float* src = ga.B1;
                        int sz = 0;
                        if (kg < K && nn < Nn) {
                            src = (kg < ga.KB1) ? (ga.B1 + (size_t)kg * ldb + nn)
                                                : (ga.B2 + (size_t)(kg - ga.KB1) * ldb + nn);
                            sz = 4;
                        }
                        cp_async4(Bb + (uint32_t)(k * B_PAD + n4 * 4 + j) * 4, src, sz);
                    }
                }
            }
        }
        CP_COMMIT();
    };

    auto compute = [&](int buf) {
        const __half* As = (const __half*)(smc + buf * STG_BYTES) + (wm * 32) * A_PAD_H;
        const float*  Bs = (const float*)(smc + buf * STG_BYTES + A_BYTES) + wn * 64;
#pragma unroll
        for (int ks = 0; ks < 2; ks++) {
            uint32_t ah[2][4];
#pragma unroll
            for (int mb = 0; mb < 2; mb++) {
#pragma unroll
                for (int r = 0; r < 4; r++) {
                    int rowq = mb * 16 + g + (r & 1) * 8;
                    int kq   = ks * 16 + t * 2 + (r >> 1) * 8;
                    ah[mb][r] = *(const uint32_t*)(As + rowq * A_PAD_H + kq);
                }
            }
            uint32_t bh[8][2];
#pragma unroll
            for (int nb = 0; nb < 8; nb++) {
#pragma unroll
                for (int r = 0; r < 2; r++) {
                    int kq = ks * 16 + t * 2 + r * 8;
                    float f0 = Bs[kq * B_PAD + nb * 8 + g];
                    float f1 = Bs[(kq + 1) * B_PAD + nb * 8 + g];
                    bh[nb][r] = f16_pack(f0, f1);
                }
            }
#pragma unroll
            for (int mb = 0; mb < 2; mb++) {
#pragma unroll
                for (int nb = 0; nb < 8; nb++) {
                    mma_f16(acc[mb][nb], ah[mb], bh[nb]);
                }
            }
        }
    };

#pragma unroll
    for (int s = 0; s < STAGES - 1; s++) issue_load(s, s);

    for (int tt = 0; tt < nT; tt++) {
        issue_load(tt + STAGES - 1, (tt + STAGES - 1) % STAGES);
        CP_WAIT(STAGES - 1);
        __syncthreads();
        compute(tt % STAGES);
        __syncthreads();
    }

    // ---- epilogue ----
#pragma unroll
    for (int mb = 0; mb < 2; mb++) {
#pragma unroll
        for (int nb = 0; nb < 8; nb++) {
            int n = n0 + wn * 64 + nb * 8 + t * 2;
            float bv0 = 0.f, bv1 = 0.f;
            if (bias) {
                if (n     < Nn) bv0 = bias[n];
                if (n + 1 < Nn) bv1 = bias[n + 1];
            }
#pragma unroll
            for (int h = 0; h < 2; h++) {
                int m = m0 + wm * 32 + mb * 16 + g + h * 8;
                float v0 = acc[mb][nb][h * 2 + 0] + bv0;
                float v1 = acc[mb][nb][h * 2 + 1] + bv1;
                if (doRelu) { v0 = fmaxf(v0, 0.f); v1 = fmaxf(v1, 0.f); }
                if (outHalf) {
                    if (n < Nn) {   // Nn even for all fp16 outputs
                        __half2 hv = __floats2half2_rn(v0, v1);
                        *(uint32_t*)((__half*)ga.C + (size_t)m * ga.ldc + n) = *(uint32_t*)&hv;
                    }
                } else {
                    float* cp = (float*)ga.C + (size_t)m * ga.ldc + n;
                    if (n     < Nn) cp[0] = v0;
                    if (n + 1 < Nn) cp[1] = v1;
                }
            }
        }
    }
}

// ---------------- appearance aggregation (CSR gather, fp16 data) ----------------
__global__ __launch_bounds__(256)
void agg_app_kernel(const __half* __restrict__ P1h, const __half* __restrict__ P2h,
                    const __half* __restrict__ SPh, const float* __restrict__ b_e,
                    const int* __restrict__ esrc, const int* __restrict__ perm,
                    const int* __restrict__ row_start, __half* __restrict__ FA)
{
    const int n = blockIdx.x;
    const int tid = threadIdx.x;
    const int start = row_start[n];
    const int nb = row_start[n + 1] - start;

    uint2 p2 = *(const uint2*)(P2h + (size_t)n * 1024 + tid * 4);
    float2 b0 = __half22float2(*(__half2*)&p2.x);
    float2 b1 = __half22float2(*(__half2*)&p2.y);
    float4 be = ((const float4*)b_e)[tid];
    float bx = b0.x + be.x, by = b0.y + be.y, bz = b1.x + be.z, bw = b1.y + be.w;

    float4 acc = make_float4(0.f, 0.f, 0.f, 0.f);
#pragma unroll 2
    for (int i = 0; i < nb; i++) {
        int e = __ldg(&perm[start + i]);
        int s = __ldg(&esrc[e]);
        uint2 a = *(const uint2*)(P1h + (size_t)s * 1024 + tid * 4);
        uint2 c = *(const uint2*)(SPh + (size_t)e * 1024 + tid * 4);
        float2 a0 = __half22float2(*(__half2*)&a.x);
        float2 a1 = __half22float2(*(__half2*)&a.y);
        float2 c0 = __half22float2(*(__half2*)&c.x);
        float2 c1 = __half22float2(*(__half2*)&c.y);
        acc.x += fmaxf(a0.x + c0.x + bx, 0.f);
        acc.y += fmaxf(a0.y + c0.y + by, 0.f);
        acc.z += fmaxf(a1.x + c1.x + bz, 0.f);
        acc.w += fmaxf(a1.y + c1.y + bw, 0.f);
    }
    float inv = 1.0f / (float)max(nb, 1);
    __half2 o0 = __floats2half2_rn(acc.x * inv, acc.y * inv);
    __half2 o1 = __floats2half2_rn(acc.z * inv, acc.w * inv);
    uint2 o; o.x = *(uint32_t*)&o0; o.y = *(uint32_t*)&o1;
    *(uint2*)(FA + (size_t)n * 2048 + 1024 + tid * 4) = o;
}

// ---------------- language aggregation (CSR gather, fp16 data) ----------------
__global__ __launch_bounds__(96)
void agg_lang_kernel(const __half* __restrict__ Q1h, const __half* __restrict__ Q2h,
                     const float* __restrict__ b_el,
                     const int* __restrict__ esrc, const int* __restrict__ perm,
                     const int* __restrict__ row_start, __half* __restrict__ WA)
{
    const int n = blockIdx.x;
    const int c4 = threadIdx.x;
    if (c4 >= DL / 4) return;
    const int start = row_start[n];
    const int nb = row_start[n + 1] - start;

    uint2 q2 = *(const uint2*)(Q2h + (size_t)n * 304 + c4 * 4);
    float2 b0 = __half22float2(*(__half2*)&q2.x);
    float2 b1 = __half22float2(*(__half2*)&q2.y);
    float4 be = ((const float4*)b_el)[c4];
    float bx = b0.x + be.x, by = b0.y + be.y, bz = b1.x + be.z, bw = b1.y + be.w;

    float4 acc = make_float4(0.f, 0.f, 0.f, 0.f);
#pragma unroll 2
    for (int i = 0; i < nb; i++) {
        int e = __ldg(&perm[start + i]);
        int s = __ldg(&esrc[e]);
        uint2 a = *(const uint2*)(Q1h + (size_t)s * 304 + c4 * 4);
        float2 a0 = __half22float2(*(__half2*)&a.x);
        float2 a1 = __half22float2(*(__half2*)&a.y);
        acc.x += fmaxf(a0.x + bx, 0.f);
        acc.y += fmaxf(a0.y + by, 0.f);
        acc.z += fmaxf(a1.x + bz, 0.f);
        acc.w += fmaxf(a1.y + bw, 0.f);
    }
    float inv = 1.0f / (float)max(nb, 1);
    __half2 o0 = __floats2half2_rn(acc.x * inv, acc.y * inv);
    __half2 o1 = __floats2half2_rn(acc.z * inv, acc.w * inv);
    uint2 o; o.x = *(uint32_t*)&o0; o.y = *(uint32_t*)&o1;
    *(uint2*)(WA + (size_t)n * 608 + 300 + c4 * 4) = o;
}

// ---------------- readout ----------------
__global__ __launch_bounds__(128)
void readout_kernel(const float* __restrict__ Rd, const float* __restrict__ Rs,
                    const float* __restrict__ SPro,
                    const int* __restrict__ rsrc, const int* __restrict__ rdst,
                    float* __restrict__ pred)
{
    int e = blockIdx.x;
    int c = threadIdx.x;
    if (c >= NC) return;
    int s = rsrc[e];
    int d = rdst[e];
    pred[(size_t)e * NC + c] = Rd[(size_t)d * NC + c] + Rs[(size_t)s * NC + c]
                             + SPro[(size_t)e * NC + c];
}

// ---------------- host launcher ----------------
extern "C" void kernel_launch(void* const* d_in, const int* in_sizes, int n_in,
                              void* d_out, int out_size)
{
    const float* feat   = (const float*)d_in[0];
    const float* w2v    = (const float*)d_in[1];
    const float* s_f    = (const float*)d_in[2];
    const float* s_f_ro = (const float*)d_in[3];
    const float* W_e    = (const float*)d_in[4];
    const float* b_e    = (const float*)d_in[5];
    const float* W_el   = (const float*)d_in[6];
    const float* b_el   = (const float*)d_in[7];
    const float* W_nu   = (const float*)d_in[8];
    const float* b_nu   = (const float*)d_in[9];
    const float* W_nul  = (const float*)d_in[10];
    const float* b_nul  = (const float*)d_in[11];
    const float* W_p    = (const float*)d_in[12];
    const float* b_p    = (const float*)d_in[13];
    const int* esrc = (const int*)d_in[14];
    const int* edst = (const int*)d_in[15];
    const int* rsrc = (const int*)d_in[16];
    const int* rdst = (const int*)d_in[17];
    float* pred = (float*)d_out;

    float* sc = nullptr;
    cudaGetSymbolAddress((void**)&sc, g_scratch);
    __half* hs = nullptr;
    cudaGetSymbolAddress((void**)&hs, g_hscratch);
    int* isc = nullptr;
    cudaGetSymbolAddress((void**)&isc, g_iscratch);

    float* RD   = sc + OFF_RD;
    float* RS   = sc + OFF_RS;
    float* SPRO = sc + OFF_SPRO;

    __half* FA    = hs + HOFF_FA;
    __half* WA    = hs + HOFF_WA;
    __half* NFA   = hs + HOFF_NFA;
    __half* P1h   = hs + HOFF_P1;
    __half* P2h   = hs + HOFF_P2;
    __half* Q1h   = hs + HOFF_Q1;
    __half* Q2h   = hs + HOFF_Q2;
    __half* SPh   = hs + HOFF_SP;
    __half* sfh   = hs + HOFF_SFH;
    __half* sfroh = hs + HOFF_SFRO;

    int* deg  = isc + IOFF_DEG;
    int* rows = isc + IOFF_RS_;
    int* cur  = isc + IOFF_CUR;
    int* perm = isc + IOFF_PERM;

    cudaFuncSetAttribute(gemm_h, cudaFuncAttributeMaxDynamicSharedMemorySize, GM_SMEM);

    const float* Ws  = W_e + (size_t)(2 * D) * D;      // spatial rows of W_e, stride D
    const float* Wp3 = W_p + (size_t)(D + DL) * NC;    // spatial rows of W_p

    // ---- conversions ----
    conv_node_kernel<<<N_NODES, 256>>>(feat, w2v, FA, WA, NFA);
    {
        size_t pairs = ((size_t)NE + NE_RO) * 8;
        conv_sf_kernel<<<(unsigned)((pairs + 255) / 256), 256>>>(s_f, s_f_ro, sfh, sfroh);
    }

    // ---- CSR build (by dst) ----
    zero_int_kernel<<<(N_NODES + 255) / 256, 256>>>(deg, N_NODES);
    hist_kernel<<<NE / 256, 256>>>(edst, deg);
    scan_kernel<<<1, 512>>>(deg, rows, cur);
    scatter_kernel<<<NE / 256, 256>>>(edst, cur, perm);

    dim3 blk(256);
    const int BIG = 1 << 28;

    // ---- spatial pre-projections ----
    {   // SP[e] = s_f @ Ws  -> fp16 [NE,1024]
        GArgs a{sfh, 16, 16, Ws, Ws, BIG, SPh, 1024};
        gemm_h<<<dim3(8, NE / 128, 1), blk, GM_SMEM>>>(a, a, D, nullptr, D, 0, 1);
    }
    {   // SPro[e] = s_f_ro @ Wp3 + b_p -> fp32 [NE_RO,117]
        GArgs a{sfroh, 16, 16, Wp3, Wp3, BIG, SPRO, NC};
        gemm_h<<<dim3(1, NE_RO / 128, 1), blk, GM_SMEM>>>(a, a, NC, b_p, NC, 0, 0);
    }

    // ---- node-level pre-projections ----
    {   // P1 = feat @ We_top ; P2 = feat @ We_mid
        GArgs a{FA, 2048, 1024, W_e, W_e, BIG, P1h, 1024};
        GArgs b{FA, 2048, 1024, W_e + (size_t)D * D, W_e, BIG, P2h, 1024};
        gemm_h<<<dim3(8, 128, 2), blk, GM_SMEM>>>(a, b, D, nullptr, D, 0, 1);
    }
    {   // Q1 = w2v @ Wel_top ; Q2 = w2v @ Wel_bot
        GArgs a{WA, 608, 300, W_el, W_el, BIG, Q1h, 304};
        GArgs b{WA, 608, 300, W_el + (size_t)DL * DL, W_el, BIG, Q2h, 304};
        gemm_h<<<dim3(3, 128, 2), blk, GM_SMEM>>>(a, b, DL, nullptr, DL, 0, 1);
    }

    // ---- aggregation (gather, no atomics) ----
    agg_app_kernel<<<N_NODES, 256>>>(P1h, P2h, SPh, b_e, esrc, perm, rows, FA);
    agg_lang_kernel<<<N_NODES, 96>>>(Q1h, Q2h, b_el, esrc, perm, rows, WA);

    // ---- node updates ----
    {   // NF = relu([feat|AGG] @ W_nu + b_nu) -> NFA cols 0..1023
        GArgs a{FA, 2048, 2048, W_nu, W_nu, BIG, NFA, 1328};
        gemm_h<<<dim3(8, 128, 1), blk, GM_SMEM>>>(a, a, D, b_nu, D, 1, 1);
    }
    {   // NFL = relu([w2v|AGGL] @ W_nul + b_nul) -> NFA cols 1024..1323
        GArgs a{WA, 608, 600, W_nul, W_nul, BIG, NFA + 1024, 1328};
        gemm_h<<<dim3(3, 128, 1), blk, GM_SMEM>>>(a, a, DL, b_nul, DL, 1, 1);
    }

    // ---- predictor pre-projections (RD & RS merged; RS via two-segment B) ----
    {
        GArgs a{NFA, 1328, 1324, W_p, W_p, BIG, RD, NC};
        GArgs b{NFA, 1328, 1324,
                W_p + (size_t)(D + DL + DS + DL) * NC,   // NF part: rows 1640..2663
                W_p + (size_t)(D + DL + DS) * NC,        // NFL part: rows 1340..1639
                1024, RS, NC};
        gemm_h<<<dim3(1, 128, 2), blk, GM_SMEM>>>(a, b, NC, nullptr, NC, 0, 0);
    }

    // ---- final edge readout ----
    readout_kernel<<<NE_RO, 128>>>(RD, RS, SPRO, rsrc, rdst, pred);
}